// round 1
// baseline (speedup 1.0000x reference)
#include <cuda_runtime.h>
#include <math.h>

#define NTOK 8192
#define NEXP 8
#define IDIM 2816
#define HDIM 1024
#define NROWS (2*NTOK)          // total routed rows (top_k=2), fixed = 16384
#define BM 64
#define BN 64
#define BK 16
#define MAX_TILES (NROWS/BM + NEXP)   // 264: worst-case M-tiles across experts

// ---- device scratch (no allocations allowed) ----
__device__ float g_h[NROWS * IDIM];        // 184.5 MB intermediate h
__device__ int   g_bin_tok[NROWS];
__device__ float g_bin_w[NROWS];
__device__ int   g_counts[NEXP];
__device__ int   g_cursor[NEXP];
__device__ int   g_tok_e[NTOK][2];
__device__ float g_tok_w[NTOK][2];
__device__ int   g_tile_e[MAX_TILES];
__device__ int   g_tile_row0[MAX_TILES];
__device__ int   g_tile_m[MAX_TILES];
__device__ int   g_ntiles;

// ---------------- init: zero expert counts ----------------
__global__ void k_init() {
    if (threadIdx.x < NEXP) g_counts[threadIdx.x] = 0;
}

// ---------------- router: softmax top-2 + renorm ----------------
// renormalized top-2 softmax weights: denominator cancels ->
// w0 = exp(l0)/(exp(l0)+exp(l1)) = 1/(1+exp(l1-l0)), w1 = 1-w0
__global__ void k_router(const float* __restrict__ logits) {
    int t = blockIdx.x * blockDim.x + threadIdx.x;
    if (t >= NTOK) return;
    float best = -INFINITY, second = -INFINITY;
    int b0 = 0, b1 = 0;
#pragma unroll
    for (int e = 0; e < NEXP; e++) {
        float v = logits[t * NEXP + e];
        if (v > best)        { second = best; b1 = b0; best = v; b0 = e; }
        else if (v > second) { second = v; b1 = e; }
    }
    float w0 = 1.0f / (1.0f + expf(second - best));
    g_tok_e[t][0] = b0;  g_tok_e[t][1] = b1;
    g_tok_w[t][0] = w0;  g_tok_w[t][1] = 1.0f - w0;
    atomicAdd(&g_counts[b0], 1);
    atomicAdd(&g_counts[b1], 1);
}

// ---------------- prefix + tile map (tiny, 1 thread) ----------------
__global__ void k_prep() {
    if (threadIdx.x != 0 || blockIdx.x != 0) return;
    int off = 0, nt = 0;
    for (int e = 0; e < NEXP; e++) {
        int c = g_counts[e];
        g_cursor[e] = off;
        for (int r = 0; r < c; r += BM) {
            g_tile_e[nt]    = e;
            g_tile_row0[nt] = off + r;
            g_tile_m[nt]    = min(BM, c - r);
            nt++;
        }
        off += c;
    }
    g_ntiles = nt;
}

// ---------------- scatter tokens into expert bins ----------------
__global__ void k_scatter() {
    int t = blockIdx.x * blockDim.x + threadIdx.x;
    if (t >= NTOK) return;
#pragma unroll
    for (int k = 0; k < 2; k++) {
        int e = g_tok_e[t][k];
        int p = atomicAdd(&g_cursor[e], 1);
        g_bin_tok[p] = t;
        g_bin_w[p]   = g_tok_w[t][k];
    }
}

// ---------------- zero output ----------------
__global__ void k_zero(float* __restrict__ out) {
    int i = blockIdx.x * blockDim.x + threadIdx.x;
    int n4 = (NTOK * HDIM) / 4;
    if (i < n4) ((float4*)out)[i] = make_float4(0.f, 0.f, 0.f, 0.f);
}

// ---------------- GEMM1: h = silu(X@W1^T) * (X@W3^T), per expert ----------------
// tile: BM x BN per C-matrix, two C matrices sharing the A tile.
// thread (ty,tx) computes 4x4 of C1 and 4x4 of C3.
__global__ void __launch_bounds__(256)
k_gemm1(const float* __restrict__ X,
        const float* __restrict__ W1,
        const float* __restrict__ W3) {
    if ((int)blockIdx.x >= g_ntiles) return;
    int te   = g_tile_e[blockIdx.x];
    int row0 = g_tile_row0[blockIdx.x];
    int mcnt = g_tile_m[blockIdx.x];
    int n0   = blockIdx.y * BN;

    __shared__ __align__(16) float As[BK][BM];
    __shared__ __align__(16) float B1s[BK][BN];
    __shared__ __align__(16) float B3s[BK][BN];
    __shared__ int s_tok[BM];

    int tid = threadIdx.x;
    if (tid < BM) s_tok[tid] = (tid < mcnt) ? g_bin_tok[row0 + tid] : -1;
    __syncthreads();

    const float* W1e = W1 + (size_t)te * IDIM * HDIM;
    const float* W3e = W3 + (size_t)te * IDIM * HDIM;

    int lr = tid >> 2;           // load row (0..63)
    int ls = (tid & 3) * 4;      // k offset within tile (0,4,8,12)
    int tx = tid & 15, ty = tid >> 4;

    int tokr = s_tok[lr];
    const float* aptr  = X   + (size_t)(tokr < 0 ? 0 : tokr) * HDIM + ls;
    const float* b1ptr = W1e + (size_t)(n0 + lr) * HDIM + ls;
    const float* b3ptr = W3e + (size_t)(n0 + lr) * HDIM + ls;

    float acc1[4][4] = {}, acc3[4][4] = {};

    for (int kt = 0; kt < HDIM; kt += BK) {
        float4 av = make_float4(0.f, 0.f, 0.f, 0.f);
        if (tokr >= 0) av = *(const float4*)(aptr + kt);
        float4 b1v = *(const float4*)(b1ptr + kt);
        float4 b3v = *(const float4*)(b3ptr + kt);
        __syncthreads();
        As[ls + 0][lr] = av.x;  As[ls + 1][lr] = av.y;
        As[ls + 2][lr] = av.z;  As[ls + 3][lr] = av.w;
        B1s[ls + 0][lr] = b1v.x; B1s[ls + 1][lr] = b1v.y;
        B1s[ls + 2][lr] = b1v.z; B1s[ls + 3][lr] = b1v.w;
        B3s[ls + 0][lr] = b3v.x; B3s[ls + 1][lr] = b3v.y;
        B3s[ls + 2][lr] = b3v.z; B3s[ls + 3][lr] = b3v.w;
        __syncthreads();
#pragma unroll
        for (int k = 0; k < BK; k++) {
            float a[4], b1[4], b3[4];
            *(float4*)a  = *(const float4*)&As[k][ty * 4];
            *(float4*)b1 = *(const float4*)&B1s[k][tx * 4];
            *(float4*)b3 = *(const float4*)&B3s[k][tx * 4];
#pragma unroll
            for (int i = 0; i < 4; i++)
#pragma unroll
                for (int j = 0; j < 4; j++) {
                    acc1[i][j] += a[i] * b1[j];
                    acc3[i][j] += a[i] * b3[j];
                }
        }
    }

    // epilogue: h = silu(c1) * c3 -> scratch (bin rows are contiguous)
#pragma unroll
    for (int i = 0; i < 4; i++) {
        int m = ty * 4 + i;
        if (m >= mcnt) continue;
        float4 hv;
        float c;
        c = acc1[i][0]; hv.x = c / (1.0f + expf(-c)) * acc3[i][0];
        c = acc1[i][1]; hv.y = c / (1.0f + expf(-c)) * acc3[i][1];
        c = acc1[i][2]; hv.z = c / (1.0f + expf(-c)) * acc3[i][2];
        c = acc1[i][3]; hv.w = c / (1.0f + expf(-c)) * acc3[i][3];
        *(float4*)&g_h[(size_t)(row0 + m) * IDIM + n0 + tx * 4] = hv;
    }
}

// ---------------- GEMM2: out[tok] += w * (h @ W2^T), per expert ----------------
__global__ void __launch_bounds__(256)
k_gemm2(const float* __restrict__ W2, float* __restrict__ out) {
    if ((int)blockIdx.x >= g_ntiles) return;
    int te   = g_tile_e[blockIdx.x];
    int row0 = g_tile_row0[blockIdx.x];
    int mcnt = g_tile_m[blockIdx.x];
    int n0   = blockIdx.y * BN;

    __shared__ __align__(16) float As[BK][BM];
    __shared__ __align__(16) float Bs[BK][BN];
    __shared__ int   s_tok[BM];
    __shared__ float s_w[BM];

    int tid = threadIdx.x;
    if (tid < BM) {
        s_tok[tid] = (tid < mcnt) ? g_bin_tok[row0 + tid] : -1;
        s_w[tid]   = (tid < mcnt) ? g_bin_w[row0 + tid] : 0.0f;
    }
    __syncthreads();

    const float* W2e = W2 + (size_t)te * HDIM * IDIM;

    int lr = tid >> 2;
    int ls = (tid & 3) * 4;
    int tx = tid & 15, ty = tid >> 4;

    bool arow_ok = (lr < mcnt);
    const float* aptr = g_h + (size_t)(row0 + (arow_ok ? lr : 0)) * IDIM + ls;
    const float* bptr = W2e + (size_t)(n0 + lr) * IDIM + ls;

    float acc[4][4] = {};

    for (int kt = 0; kt < IDIM; kt += BK) {
        float4 av = make_float4(0.f, 0.f, 0.f, 0.f);
        if (arow_ok) av = *(const float4*)(aptr + kt);
        float4 bv = *(const float4*)(bptr + kt);
        __syncthreads();
        As[ls + 0][lr] = av.x; As[ls + 1][lr] = av.y;
        As[ls + 2][lr] = av.z; As[ls + 3][lr] = av.w;
        Bs[ls + 0][lr] = bv.x; Bs[ls + 1][lr] = bv.y;
        Bs[ls + 2][lr] = bv.z; Bs[ls + 3][lr] = bv.w;
        __syncthreads();
#pragma unroll
        for (int k = 0; k < BK; k++) {
            float a[4], b[4];
            *(float4*)a = *(const float4*)&As[k][ty * 4];
            *(float4*)b = *(const float4*)&Bs[k][tx * 4];
#pragma unroll
            for (int i = 0; i < 4; i++)
#pragma unroll
                for (int j = 0; j < 4; j++)
                    acc[i][j] += a[i] * b[j];
        }
    }

#pragma unroll
    for (int i = 0; i < 4; i++) {
        int m = ty * 4 + i;
        if (m >= mcnt) continue;
        int tok = s_tok[m];
        float w = s_w[m];
        float* op = out + (size_t)tok * HDIM + n0 + tx * 4;
#pragma unroll
        for (int j = 0; j < 4; j++)
            atomicAdd(op + j, acc[i][j] * w);
    }
}

// ---------------- launch ----------------
extern "C" void kernel_launch(void* const* d_in, const int* in_sizes, int n_in,
                              void* d_out, int out_size) {
    const float* X  = (const float*)d_in[0];  // [T,H]
    const float* RL = (const float*)d_in[1];  // [T,E]
    const float* W1 = (const float*)d_in[2];  // [E,I,H]
    const float* W3 = (const float*)d_in[3];  // [E,I,H]
    const float* W2 = (const float*)d_in[4];  // [E,H,I]
    float* out = (float*)d_out;               // [T,H]

    k_init<<<1, 32>>>();
    k_router<<<NTOK / 256, 256>>>(RL);
    k_prep<<<1, 1>>>();
    k_scatter<<<NTOK / 256, 256>>>();

    dim3 g1(MAX_TILES, IDIM / BN);   // 264 x 44
    k_gemm1<<<g1, 256>>>(X, W1, W3);

    k_zero<<<(NTOK * HDIM / 4 + 255) / 256, 256>>>(out);

    dim3 g2(MAX_TILES, HDIM / BN);   // 264 x 16
    k_gemm2<<<g2, 256>>>(W2, out);
}

// round 2
// speedup vs baseline: 1.0004x; 1.0004x over previous
#include <cuda_runtime.h>
#include <math.h>

#define NTOK 8192
#define NEXP 8
#define IDIM 2816
#define HDIM 1024
#define NROWS (2*NTOK)          // total routed rows (top_k=2), fixed = 16384
#define BM 64
#define BN 64
#define BK 16
#define MAX_TILES (NROWS/BM + NEXP)   // 264: worst-case M-tiles across experts

// ---- device scratch (no allocations allowed) ----
__device__ float g_h[NROWS * IDIM];        // 184.5 MB intermediate h
__device__ int   g_bin_tok[NROWS];
__device__ float g_bin_w[NROWS];
__device__ int   g_counts[NEXP];
__device__ int   g_cursor[NEXP];
__device__ int   g_tok_e[NTOK][2];
__device__ float g_tok_w[NTOK][2];
__device__ int   g_tile_e[MAX_TILES];
__device__ int   g_tile_row0[MAX_TILES];
__device__ int   g_tile_m[MAX_TILES];
__device__ int   g_ntiles;

// ---------------- init: zero expert counts ----------------
__global__ void k_init() {
    if (threadIdx.x < NEXP) g_counts[threadIdx.x] = 0;
}

// ---------------- router: softmax top-2 + renorm ----------------
// renormalized top-2 softmax weights: denominator cancels ->
// w0 = exp(l0)/(exp(l0)+exp(l1)) = 1/(1+exp(l1-l0)), w1 = 1-w0
__global__ void k_router(const float* __restrict__ logits) {
    int t = blockIdx.x * blockDim.x + threadIdx.x;
    if (t >= NTOK) return;
    float best = -INFINITY, second = -INFINITY;
    int b0 = 0, b1 = 0;
#pragma unroll
    for (int e = 0; e < NEXP; e++) {
        float v = logits[t * NEXP + e];
        if (v > best)        { second = best; b1 = b0; best = v; b0 = e; }
        else if (v > second) { second = v; b1 = e; }
    }
    float w0 = 1.0f / (1.0f + expf(second - best));
    g_tok_e[t][0] = b0;  g_tok_e[t][1] = b1;
    g_tok_w[t][0] = w0;  g_tok_w[t][1] = 1.0f - w0;
    atomicAdd(&g_counts[b0], 1);
    atomicAdd(&g_counts[b1], 1);
}

// ---------------- prefix + tile map (tiny, 1 thread) ----------------
__global__ void k_prep() {
    if (threadIdx.x != 0 || blockIdx.x != 0) return;
    int off = 0, nt = 0;
    for (int e = 0; e < NEXP; e++) {
        int c = g_counts[e];
        g_cursor[e] = off;
        for (int r = 0; r < c; r += BM) {
            g_tile_e[nt]    = e;
            g_tile_row0[nt] = off + r;
            g_tile_m[nt]    = min(BM, c - r);
            nt++;
        }
        off += c;
    }
    g_ntiles = nt;
}

// ---------------- scatter tokens into expert bins ----------------
__global__ void k_scatter() {
    int t = blockIdx.x * blockDim.x + threadIdx.x;
    if (t >= NTOK) return;
#pragma unroll
    for (int k = 0; k < 2; k++) {
        int e = g_tok_e[t][k];
        int p = atomicAdd(&g_cursor[e], 1);
        g_bin_tok[p] = t;
        g_bin_w[p]   = g_tok_w[t][k];
    }
}

// ---------------- zero output ----------------
__global__ void k_zero(float* __restrict__ out) {
    int i = blockIdx.x * blockDim.x + threadIdx.x;
    int n4 = (NTOK * HDIM) / 4;
    if (i < n4) ((float4*)out)[i] = make_float4(0.f, 0.f, 0.f, 0.f);
}

// ---------------- GEMM1: h = silu(X@W1^T) * (X@W3^T), per expert ----------------
// tile: BM x BN per C-matrix, two C matrices sharing the A tile.
// thread (ty,tx) computes 4x4 of C1 and 4x4 of C3.
__global__ void __launch_bounds__(256)
k_gemm1(const float* __restrict__ X,
        const float* __restrict__ W1,
        const float* __restrict__ W3) {
    if ((int)blockIdx.x >= g_ntiles) return;
    int te   = g_tile_e[blockIdx.x];
    int row0 = g_tile_row0[blockIdx.x];
    int mcnt = g_tile_m[blockIdx.x];
    int n0   = blockIdx.y * BN;

    __shared__ __align__(16) float As[BK][BM];
    __shared__ __align__(16) float B1s[BK][BN];
    __shared__ __align__(16) float B3s[BK][BN];
    __shared__ int s_tok[BM];

    int tid = threadIdx.x;
    if (tid < BM) s_tok[tid] = (tid < mcnt) ? g_bin_tok[row0 + tid] : -1;
    __syncthreads();

    const float* W1e = W1 + (size_t)te * IDIM * HDIM;
    const float* W3e = W3 + (size_t)te * IDIM * HDIM;

    int lr = tid >> 2;           // load row (0..63)
    int ls = (tid & 3) * 4;      // k offset within tile (0,4,8,12)
    int tx = tid & 15, ty = tid >> 4;

    int tokr = s_tok[lr];
    const float* aptr  = X   + (size_t)(tokr < 0 ? 0 : tokr) * HDIM + ls;
    const float* b1ptr = W1e + (size_t)(n0 + lr) * HDIM + ls;
    const float* b3ptr = W3e + (size_t)(n0 + lr) * HDIM + ls;

    float acc1[4][4] = {}, acc3[4][4] = {};

    for (int kt = 0; kt < HDIM; kt += BK) {
        float4 av = make_float4(0.f, 0.f, 0.f, 0.f);
        if (tokr >= 0) av = *(const float4*)(aptr + kt);
        float4 b1v = *(const float4*)(b1ptr + kt);
        float4 b3v = *(const float4*)(b3ptr + kt);
        __syncthreads();
        As[ls + 0][lr] = av.x;  As[ls + 1][lr] = av.y;
        As[ls + 2][lr] = av.z;  As[ls + 3][lr] = av.w;
        B1s[ls + 0][lr] = b1v.x; B1s[ls + 1][lr] = b1v.y;
        B1s[ls + 2][lr] = b1v.z; B1s[ls + 3][lr] = b1v.w;
        B3s[ls + 0][lr] = b3v.x; B3s[ls + 1][lr] = b3v.y;
        B3s[ls + 2][lr] = b3v.z; B3s[ls + 3][lr] = b3v.w;
        __syncthreads();
#pragma unroll
        for (int k = 0; k < BK; k++) {
            float a[4], b1[4], b3[4];
            *(float4*)a  = *(const float4*)&As[k][ty * 4];
            *(float4*)b1 = *(const float4*)&B1s[k][tx * 4];
            *(float4*)b3 = *(const float4*)&B3s[k][tx * 4];
#pragma unroll
            for (int i = 0; i < 4; i++)
#pragma unroll
                for (int j = 0; j < 4; j++) {
                    acc1[i][j] += a[i] * b1[j];
                    acc3[i][j] += a[i] * b3[j];
                }
        }
    }

    // epilogue: h = silu(c1) * c3 -> scratch (bin rows are contiguous)
#pragma unroll
    for (int i = 0; i < 4; i++) {
        int m = ty * 4 + i;
        if (m >= mcnt) continue;
        float4 hv;
        float c;
        c = acc1[i][0]; hv.x = c / (1.0f + expf(-c)) * acc3[i][0];
        c = acc1[i][1]; hv.y = c / (1.0f + expf(-c)) * acc3[i][1];
        c = acc1[i][2]; hv.z = c / (1.0f + expf(-c)) * acc3[i][2];
        c = acc1[i][3]; hv.w = c / (1.0f + expf(-c)) * acc3[i][3];
        *(float4*)&g_h[(size_t)(row0 + m) * IDIM + n0 + tx * 4] = hv;
    }
}

// ---------------- GEMM2: out[tok] += w * (h @ W2^T), per expert ----------------
__global__ void __launch_bounds__(256)
k_gemm2(const float* __restrict__ W2, float* __restrict__ out) {
    if ((int)blockIdx.x >= g_ntiles) return;
    int te   = g_tile_e[blockIdx.x];
    int row0 = g_tile_row0[blockIdx.x];
    int mcnt = g_tile_m[blockIdx.x];
    int n0   = blockIdx.y * BN;

    __shared__ __align__(16) float As[BK][BM];
    __shared__ __align__(16) float Bs[BK][BN];
    __shared__ int   s_tok[BM];
    __shared__ float s_w[BM];

    int tid = threadIdx.x;
    if (tid < BM) {
        s_tok[tid] = (tid < mcnt) ? g_bin_tok[row0 + tid] : -1;
        s_w[tid]   = (tid < mcnt) ? g_bin_w[row0 + tid] : 0.0f;
    }
    __syncthreads();

    const float* W2e = W2 + (size_t)te * HDIM * IDIM;

    int lr = tid >> 2;
    int ls = (tid & 3) * 4;
    int tx = tid & 15, ty = tid >> 4;

    bool arow_ok = (lr < mcnt);
    const float* aptr = g_h + (size_t)(row0 + (arow_ok ? lr : 0)) * IDIM + ls;
    const float* bptr = W2e + (size_t)(n0 + lr) * IDIM + ls;

    float acc[4][4] = {};

    for (int kt = 0; kt < IDIM; kt += BK) {
        float4 av = make_float4(0.f, 0.f, 0.f, 0.f);
        if (arow_ok) av = *(const float4*)(aptr + kt);
        float4 bv = *(const float4*)(bptr + kt);
        __syncthreads();
        As[ls + 0][lr] = av.x; As[ls + 1][lr] = av.y;
        As[ls + 2][lr] = av.z; As[ls + 3][lr] = av.w;
        Bs[ls + 0][lr] = bv.x; Bs[ls + 1][lr] = bv.y;
        Bs[ls + 2][lr] = bv.z; Bs[ls + 3][lr] = bv.w;
        __syncthreads();
#pragma unroll
        for (int k = 0; k < BK; k++) {
            float a[4], b[4];
            *(float4*)a = *(const float4*)&As[k][ty * 4];
            *(float4*)b = *(const float4*)&Bs[k][tx * 4];
#pragma unroll
            for (int i = 0; i < 4; i++)
#pragma unroll
                for (int j = 0; j < 4; j++)
                    acc[i][j] += a[i] * b[j];
        }
    }

#pragma unroll
    for (int i = 0; i < 4; i++) {
        int m = ty * 4 + i;
        if (m >= mcnt) continue;
        int tok = s_tok[m];
        float w = s_w[m];
        float* op = out + (size_t)tok * HDIM + n0 + tx * 4;
#pragma unroll
        for (int j = 0; j < 4; j++)
            atomicAdd(op + j, acc[i][j] * w);
    }
}

// ---------------- launch ----------------
extern "C" void kernel_launch(void* const* d_in, const int* in_sizes, int n_in,
                              void* d_out, int out_size) {
    const float* X  = (const float*)d_in[0];  // [T,H]
    const float* RL = (const float*)d_in[1];  // [T,E]
    const float* W1 = (const float*)d_in[2];  // [E,I,H]
    const float* W3 = (const float*)d_in[3];  // [E,I,H]
    const float* W2 = (const float*)d_in[4];  // [E,H,I]
    float* out = (float*)d_out;               // [T,H]

    k_init<<<1, 32>>>();
    k_router<<<NTOK / 256, 256>>>(RL);
    k_prep<<<1, 1>>>();
    k_scatter<<<NTOK / 256, 256>>>();

    dim3 g1(MAX_TILES, IDIM / BN);   // 264 x 44
    k_gemm1<<<g1, 256>>>(X, W1, W3);

    k_zero<<<(NTOK * HDIM / 4 + 255) / 256, 256>>>(out);

    dim3 g2(MAX_TILES, HDIM / BN);   // 264 x 16
    k_gemm2<<<g2, 256>>>(W2, out);
}

// round 3
// speedup vs baseline: 3.0600x; 3.0589x over previous
#include <cuda_runtime.h>
#include <math.h>

#define NTOK 8192
#define NEXP 8
#define IDIM 2816
#define HDIM 1024
#define NROWS (2*NTOK)             // total routed rows (top_k=2) = 16384
#define BM 128
#define BK 16
#define SMSTRIDE 20                // row stride in smem floats (conflict-free frag loads)
#define MAX_TILES (NROWS/BM + NEXP)   // 136 worst-case M-tiles

// ---- device scratch ----
__device__ float g_h[NROWS * IDIM];        // 184.5 MB intermediate h (fp32)
__device__ int   g_bin_tok[NROWS];
__device__ float g_bin_w[NROWS];
__device__ int   g_counts[NEXP];
__device__ int   g_cursor[NEXP];
__device__ int   g_tok_e[NTOK][2];
__device__ float g_tok_w[NTOK][2];
__device__ int   g_tile_e[MAX_TILES];
__device__ int   g_tile_row0[MAX_TILES];
__device__ int   g_tile_m[MAX_TILES];
__device__ int   g_ntiles;

// ---------------- helpers ----------------
__device__ __forceinline__ unsigned f2tf(float x) {
    unsigned u;
    asm("cvt.rna.tf32.f32 %0, %1;" : "=r"(u) : "f"(x));
    return u;
}

__device__ __forceinline__ void mma_tf32(float* c, const unsigned* a, const unsigned* b) {
    asm volatile(
        "mma.sync.aligned.m16n8k8.row.col.f32.tf32.tf32.f32 "
        "{%0,%1,%2,%3},{%4,%5,%6,%7},{%8,%9},{%0,%1,%2,%3};"
        : "+f"(c[0]), "+f"(c[1]), "+f"(c[2]), "+f"(c[3])
        : "r"(a[0]), "r"(a[1]), "r"(a[2]), "r"(a[3]), "r"(b[0]), "r"(b[1]));
}

__device__ __forceinline__ void sts_tf4(float* dst, float4 v) {
    // convert to tf32 bits and store 16B
    uint4 u;
    u.x = f2tf(v.x); u.y = f2tf(v.y); u.z = f2tf(v.z); u.w = f2tf(v.w);
    *(uint4*)dst = u;
}

// ---------------- init ----------------
__global__ void k_init() {
    if (threadIdx.x < NEXP) g_counts[threadIdx.x] = 0;
}

// ---------------- router: softmax top-2 + renorm ----------------
__global__ void k_router(const float* __restrict__ logits) {
    int t = blockIdx.x * blockDim.x + threadIdx.x;
    if (t >= NTOK) return;
    float best = -INFINITY, second = -INFINITY;
    int b0 = 0, b1 = 0;
#pragma unroll
    for (int e = 0; e < NEXP; e++) {
        float v = logits[t * NEXP + e];
        if (v > best)        { second = best; b1 = b0; best = v; b0 = e; }
        else if (v > second) { second = v; b1 = e; }
    }
    float w0 = 1.0f / (1.0f + expf(second - best));
    g_tok_e[t][0] = b0;  g_tok_e[t][1] = b1;
    g_tok_w[t][0] = w0;  g_tok_w[t][1] = 1.0f - w0;
    atomicAdd(&g_counts[b0], 1);
    atomicAdd(&g_counts[b1], 1);
}

// ---------------- prefix + tile map ----------------
__global__ void k_prep() {
    if (threadIdx.x != 0 || blockIdx.x != 0) return;
    int off = 0, nt = 0;
    for (int e = 0; e < NEXP; e++) {
        int c = g_counts[e];
        g_cursor[e] = off;
        for (int r = 0; r < c; r += BM) {
            g_tile_e[nt]    = e;
            g_tile_row0[nt] = off + r;
            g_tile_m[nt]    = min(BM, c - r);
            nt++;
        }
        off += c;
    }
    g_ntiles = nt;
}

// ---------------- scatter ----------------
__global__ void k_scatter() {
    int t = blockIdx.x * blockDim.x + threadIdx.x;
    if (t >= NTOK) return;
#pragma unroll
    for (int k = 0; k < 2; k++) {
        int e = g_tok_e[t][k];
        int p = atomicAdd(&g_cursor[e], 1);
        g_bin_tok[p] = t;
        g_bin_w[p]   = g_tok_w[t][k];
    }
}

// ---------------- zero output ----------------
__global__ void k_zero(float* __restrict__ out) {
    int i = blockIdx.x * blockDim.x + threadIdx.x;
    int n4 = (NTOK * HDIM) / 4;
    if (i < n4) ((float4*)out)[i] = make_float4(0.f, 0.f, 0.f, 0.f);
}

// =====================================================================
// GEMM1 (TF32 mma): h = silu(X@W1^T) * (X@W3^T)
// block 128(M) x 128(N), BK=16, 8 warps 2(M)x4(N), warp tile 64x32.
// =====================================================================
#define G1_SMBUF (BM * SMSTRIDE)   // 2560 floats per matrix per buffer

__global__ void __launch_bounds__(256)
k_gemm1(const float* __restrict__ X,
        const float* __restrict__ W1,
        const float* __restrict__ W3) {
    if ((int)blockIdx.y >= g_ntiles) return;
    int te   = g_tile_e[blockIdx.y];
    int row0 = g_tile_row0[blockIdx.y];
    int mcnt = g_tile_m[blockIdx.y];
    int nb   = blockIdx.x * 128;

    extern __shared__ float sm[];
    float* As  = sm;                  // [2][BM][SMSTRIDE]
    float* B1s = sm + 2 * G1_SMBUF;
    float* B3s = sm + 4 * G1_SMBUF;
    __shared__ int s_tok[BM];

    int tid = threadIdx.x;
    if (tid < BM) s_tok[tid] = (tid < mcnt) ? g_bin_tok[row0 + tid] : 0;
    __syncthreads();

    const float* W1e = W1 + (size_t)te * IDIM * HDIM;
    const float* W3e = W3 + (size_t)te * IDIM * HDIM;

    // loader mapping: kc = tid&3 (float4 within 16k), r = tid>>2 (0..63), 2 iters
    int kc = tid & 3;
    int lr = tid >> 2;
    int tok0 = s_tok[lr];
    int tok1 = s_tok[lr + 64];
    const float* ap0 = X + (size_t)tok0 * HDIM + kc * 4;
    const float* ap1 = X + (size_t)tok1 * HDIM + kc * 4;
    const float* b1p0 = W1e + (size_t)(nb + lr) * HDIM + kc * 4;
    const float* b1p1 = W1e + (size_t)(nb + lr + 64) * HDIM + kc * 4;
    const float* b3p0 = W3e + (size_t)(nb + lr) * HDIM + kc * 4;
    const float* b3p1 = W3e + (size_t)(nb + lr + 64) * HDIM + kc * 4;

    // warp / lane mapping
    int warpId = tid >> 5;
    int lane = tid & 31;
    int wm = (warpId & 1) * 64;   // warp m offset
    int wn = (warpId >> 1) * 32;  // warp n offset
    int fr = lane >> 2;
    int fc = lane & 3;

    float acc1[4][4][4];
    float acc3[4][4][4];
#pragma unroll
    for (int i = 0; i < 4; i++)
#pragma unroll
        for (int j = 0; j < 4; j++)
#pragma unroll
            for (int k = 0; k < 4; k++) { acc1[i][j][k] = 0.f; acc3[i][j][k] = 0.f; }

    float4 pa0, pa1, pb10, pb11, pb30, pb31;

    // prefetch kt=0
    pa0 = *(const float4*)(ap0);   pa1 = *(const float4*)(ap1);
    pb10 = *(const float4*)(b1p0); pb11 = *(const float4*)(b1p1);
    pb30 = *(const float4*)(b3p0); pb31 = *(const float4*)(b3p1);

    int buf = 0;
    {
        float* A = As;  float* B1 = B1s; float* B3 = B3s;
        sts_tf4(A + lr * SMSTRIDE + kc * 4, pa0);
        sts_tf4(A + (lr + 64) * SMSTRIDE + kc * 4, pa1);
        sts_tf4(B1 + lr * SMSTRIDE + kc * 4, pb10);
        sts_tf4(B1 + (lr + 64) * SMSTRIDE + kc * 4, pb11);
        sts_tf4(B3 + lr * SMSTRIDE + kc * 4, pb30);
        sts_tf4(B3 + (lr + 64) * SMSTRIDE + kc * 4, pb31);
    }
    __syncthreads();

    for (int kt = 0; kt < HDIM; kt += BK) {
        bool has_next = (kt + BK) < HDIM;
        if (has_next) {
            int ko = kt + BK;
            pa0 = *(const float4*)(ap0 + ko);   pa1 = *(const float4*)(ap1 + ko);
            pb10 = *(const float4*)(b1p0 + ko); pb11 = *(const float4*)(b1p1 + ko);
            pb30 = *(const float4*)(b3p0 + ko); pb31 = *(const float4*)(b3p1 + ko);
        }
        // compute on buf
        const float* A  = As  + buf * G1_SMBUF;
        const float* B1 = B1s + buf * G1_SMBUF;
        const float* B3 = B3s + buf * G1_SMBUF;
#pragma unroll
        for (int kk = 0; kk < BK; kk += 8) {
            unsigned a[4][4];
#pragma unroll
            for (int mt = 0; mt < 4; mt++) {
                const float* ab = A + (wm + mt * 16 + fr) * SMSTRIDE + kk + fc;
                a[mt][0] = __float_as_uint(ab[0]);
                a[mt][1] = __float_as_uint(ab[8 * SMSTRIDE]);
                a[mt][2] = __float_as_uint(ab[4]);
                a[mt][3] = __float_as_uint(ab[8 * SMSTRIDE + 4]);
            }
#pragma unroll
            for (int nt = 0; nt < 4; nt++) {
                const float* bb1 = B1 + (wn + nt * 8 + fr) * SMSTRIDE + kk + fc;
                const float* bb3 = B3 + (wn + nt * 8 + fr) * SMSTRIDE + kk + fc;
                unsigned b1f[2], b3f[2];
                b1f[0] = __float_as_uint(bb1[0]); b1f[1] = __float_as_uint(bb1[4]);
                b3f[0] = __float_as_uint(bb3[0]); b3f[1] = __float_as_uint(bb3[4]);
#pragma unroll
                for (int mt = 0; mt < 4; mt++) {
                    mma_tf32(acc1[mt][nt], a[mt], b1f);
                    mma_tf32(acc3[mt][nt], a[mt], b3f);
                }
            }
        }
        if (has_next) {
            float* A2  = As  + (buf ^ 1) * G1_SMBUF;
            float* B12 = B1s + (buf ^ 1) * G1_SMBUF;
            float* B32 = B3s + (buf ^ 1) * G1_SMBUF;
            sts_tf4(A2 + lr * SMSTRIDE + kc * 4, pa0);
            sts_tf4(A2 + (lr + 64) * SMSTRIDE + kc * 4, pa1);
            sts_tf4(B12 + lr * SMSTRIDE + kc * 4, pb10);
            sts_tf4(B12 + (lr + 64) * SMSTRIDE + kc * 4, pb11);
            sts_tf4(B32 + lr * SMSTRIDE + kc * 4, pb30);
            sts_tf4(B32 + (lr + 64) * SMSTRIDE + kc * 4, pb31);
        }
        __syncthreads();
        buf ^= 1;
    }

    // epilogue: h = silu(c1) * c3
#pragma unroll
    for (int mt = 0; mt < 4; mt++) {
        int m_lo = wm + mt * 16 + fr;
        int m_hi = m_lo + 8;
#pragma unroll
        for (int nt = 0; nt < 4; nt++) {
            int col = nb + wn + nt * 8 + fc * 2;
            if (m_lo < mcnt) {
                float c0 = acc1[mt][nt][0], c1 = acc1[mt][nt][1];
                float2 hv;
                hv.x = c0 / (1.0f + expf(-c0)) * acc3[mt][nt][0];
                hv.y = c1 / (1.0f + expf(-c1)) * acc3[mt][nt][1];
                *(float2*)&g_h[(size_t)(row0 + m_lo) * IDIM + col] = hv;
            }
            if (m_hi < mcnt) {
                float c2 = acc1[mt][nt][2], c3 = acc1[mt][nt][3];
                float2 hv;
                hv.x = c2 / (1.0f + expf(-c2)) * acc3[mt][nt][2];
                hv.y = c3 / (1.0f + expf(-c3)) * acc3[mt][nt][3];
                *(float2*)&g_h[(size_t)(row0 + m_hi) * IDIM + col] = hv;
            }
        }
    }
}

// =====================================================================
// GEMM2 (TF32 mma): out[tok] += w * (h @ W2^T)
// block 128(M) x 128(N), BK=16, same warp layout, single C.
// =====================================================================
__global__ void __launch_bounds__(256)
k_gemm2(const float* __restrict__ W2, float* __restrict__ out) {
    if ((int)blockIdx.y >= g_ntiles) return;
    int te   = g_tile_e[blockIdx.y];
    int row0 = g_tile_row0[blockIdx.y];
    int mcnt = g_tile_m[blockIdx.y];
    int nb   = blockIdx.x * 128;

    __shared__ float As[2][G1_SMBUF];
    __shared__ float Bs[2][G1_SMBUF];
    __shared__ int   s_tok[BM];
    __shared__ float s_w[BM];

    int tid = threadIdx.x;
    if (tid < BM) {
        s_tok[tid] = (tid < mcnt) ? g_bin_tok[row0 + tid] : 0;
        s_w[tid]   = (tid < mcnt) ? g_bin_w[row0 + tid] : 0.0f;
    }
    __syncthreads();

    const float* W2e = W2 + (size_t)te * HDIM * IDIM;

    int kc = tid & 3;
    int lr = tid >> 2;
    int r0e = (lr      < mcnt) ? lr      : 0;
    int r1e = (lr + 64 < mcnt) ? lr + 64 : 0;
    const float* ap0 = g_h + (size_t)(row0 + r0e) * IDIM + kc * 4;
    const float* ap1 = g_h + (size_t)(row0 + r1e) * IDIM + kc * 4;
    const float* bp0 = W2e + (size_t)(nb + lr) * IDIM + kc * 4;
    const float* bp1 = W2e + (size_t)(nb + lr + 64) * IDIM + kc * 4;

    int warpId = tid >> 5;
    int lane = tid & 31;
    int wm = (warpId & 1) * 64;
    int wn = (warpId >> 1) * 32;
    int fr = lane >> 2;
    int fc = lane & 3;

    float acc[4][4][4];
#pragma unroll
    for (int i = 0; i < 4; i++)
#pragma unroll
        for (int j = 0; j < 4; j++)
#pragma unroll
            for (int k = 0; k < 4; k++) acc[i][j][k] = 0.f;

    float4 pa0, pa1, pb0, pb1;
    pa0 = *(const float4*)(ap0); pa1 = *(const float4*)(ap1);
    pb0 = *(const float4*)(bp0); pb1 = *(const float4*)(bp1);

    {
        sts_tf4(&As[0][lr * SMSTRIDE + kc * 4], pa0);
        sts_tf4(&As[0][(lr + 64) * SMSTRIDE + kc * 4], pa1);
        sts_tf4(&Bs[0][lr * SMSTRIDE + kc * 4], pb0);
        sts_tf4(&Bs[0][(lr + 64) * SMSTRIDE + kc * 4], pb1);
    }
    __syncthreads();

    int buf = 0;
    for (int kt = 0; kt < IDIM; kt += BK) {
        bool has_next = (kt + BK) < IDIM;
        if (has_next) {
            int ko = kt + BK;
            pa0 = *(const float4*)(ap0 + ko); pa1 = *(const float4*)(ap1 + ko);
            pb0 = *(const float4*)(bp0 + ko); pb1 = *(const float4*)(bp1 + ko);
        }
        const float* A = As[buf];
        const float* B = Bs[buf];
#pragma unroll
        for (int kk = 0; kk < BK; kk += 8) {
            unsigned a[4][4];
#pragma unroll
            for (int mt = 0; mt < 4; mt++) {
                const float* ab = A + (wm + mt * 16 + fr) * SMSTRIDE + kk + fc;
                a[mt][0] = __float_as_uint(ab[0]);
                a[mt][1] = __float_as_uint(ab[8 * SMSTRIDE]);
                a[mt][2] = __float_as_uint(ab[4]);
                a[mt][3] = __float_as_uint(ab[8 * SMSTRIDE + 4]);
            }
#pragma unroll
            for (int nt = 0; nt < 4; nt++) {
                const float* bb = B + (wn + nt * 8 + fr) * SMSTRIDE + kk + fc;
                unsigned bf[2];
                bf[0] = __float_as_uint(bb[0]); bf[1] = __float_as_uint(bb[4]);
#pragma unroll
                for (int mt = 0; mt < 4; mt++)
                    mma_tf32(acc[mt][nt], a[mt], bf);
            }
        }
        if (has_next) {
            sts_tf4(&As[buf ^ 1][lr * SMSTRIDE + kc * 4], pa0);
            sts_tf4(&As[buf ^ 1][(lr + 64) * SMSTRIDE + kc * 4], pa1);
            sts_tf4(&Bs[buf ^ 1][lr * SMSTRIDE + kc * 4], pb0);
            sts_tf4(&Bs[buf ^ 1][(lr + 64) * SMSTRIDE + kc * 4], pb1);
        }
        __syncthreads();
        buf ^= 1;
    }

    // epilogue: weighted atomic scatter to tokens
#pragma unroll
    for (int mt = 0; mt < 4; mt++) {
        int m_lo = wm + mt * 16 + fr;
        int m_hi = m_lo + 8;
#pragma unroll
        for (int nt = 0; nt < 4; nt++) {
            int col = nb + wn + nt * 8 + fc * 2;
            if (m_lo < mcnt) {
                int tok = s_tok[m_lo]; float w = s_w[m_lo];
                float* op = out + (size_t)tok * HDIM + col;
                atomicAdd(op,     acc[mt][nt][0] * w);
                atomicAdd(op + 1, acc[mt][nt][1] * w);
            }
            if (m_hi < mcnt) {
                int tok = s_tok[m_hi]; float w = s_w[m_hi];
                float* op = out + (size_t)tok * HDIM + col;
                atomicAdd(op,     acc[mt][nt][2] * w);
                atomicAdd(op + 1, acc[mt][nt][3] * w);
            }
        }
    }
}

// ---------------- launch ----------------
extern "C" void kernel_launch(void* const* d_in, const int* in_sizes, int n_in,
                              void* d_out, int out_size) {
    const float* X  = (const float*)d_in[0];  // [T,H]
    const float* RL = (const float*)d_in[1];  // [T,E]
    const float* W1 = (const float*)d_in[2];  // [E,I,H]
    const float* W3 = (const float*)d_in[3];  // [E,I,H]
    const float* W2 = (const float*)d_in[4];  // [E,H,I]
    float* out = (float*)d_out;               // [T,H]

    static const int g1_smem = 6 * G1_SMBUF * sizeof(float);  // 61440 B
    cudaFuncSetAttribute(k_gemm1, cudaFuncAttributeMaxDynamicSharedMemorySize, g1_smem);

    k_init<<<1, 32>>>();
    k_router<<<NTOK / 256, 256>>>(RL);
    k_prep<<<1, 1>>>();
    k_scatter<<<NTOK / 256, 256>>>();

    dim3 g1(IDIM / 128, MAX_TILES);   // 22 x 136
    k_gemm1<<<g1, 256, g1_smem>>>(X, W1, W3);

    k_zero<<<(NTOK * HDIM / 4 + 255) / 256, 256>>>(out);

    dim3 g2(HDIM / 128, MAX_TILES);   // 8 x 136
    k_gemm2<<<g2, 256>>>(W2, out);
}

// round 5
// speedup vs baseline: 5.9859x; 1.9562x over previous
#include <cuda_runtime.h>
#include <cuda_fp16.h>
#include <math.h>
#include <stdint.h>

#define NTOK 8192
#define NEXP 8
#define IDIM 2816
#define HDIM 1024
#define NROWS (2*NTOK)                 // 16384 routed rows
#define BM 128
#define BK 32                          // halfs of K per smem stage
#define STRH 40                        // smem row stride in halfs (80B) -> conflict-free frags
#define TILE_B (BM * STRH * 2)         // 10240 bytes per tile buffer
#define MAX_TILES (NROWS/BM + NEXP)    // 136

// ---- device scratch ----
__device__ __half g_h[(size_t)NROWS * IDIM];   // 92 MB intermediate h (fp16)
__device__ int   g_bin_tok[NROWS];
__device__ float g_bin_w[NROWS];
__device__ int   g_counts[NEXP];
__device__ int   g_cursor[NEXP];
__device__ int   g_tok_e[NTOK][2];
__device__ float g_tok_w[NTOK][2];
__device__ int   g_tile_e[MAX_TILES];
__device__ int   g_tile_row0[MAX_TILES];
__device__ int   g_tile_m[MAX_TILES];
__device__ int   g_ntiles;

// ---------------- helpers ----------------
__device__ __forceinline__ void mma_f16(float* c, const uint32_t* a, const uint32_t* b) {
    asm volatile(
        "mma.sync.aligned.m16n8k16.row.col.f32.f16.f16.f32 "
        "{%0,%1,%2,%3},{%4,%5,%6,%7},{%8,%9},{%0,%1,%2,%3};"
        : "+f"(c[0]), "+f"(c[1]), "+f"(c[2]), "+f"(c[3])
        : "r"(a[0]), "r"(a[1]), "r"(a[2]), "r"(a[3]), "r"(b[0]), "r"(b[1]));
}
__device__ __forceinline__ uint2 f4_to_h4(float4 v) {
    __half2 lo = __floats2half2_rn(v.x, v.y);
    __half2 hi = __floats2half2_rn(v.z, v.w);
    uint2 u;
    u.x = *(uint32_t*)&lo;
    u.y = *(uint32_t*)&hi;
    return u;
}

// ---------------- small kernels ----------------
__global__ void k_init() {
    if (threadIdx.x < NEXP) g_counts[threadIdx.x] = 0;
}

__global__ void k_router(const float* __restrict__ logits) {
    int t = blockIdx.x * blockDim.x + threadIdx.x;
    if (t >= NTOK) return;
    float best = -INFINITY, second = -INFINITY;
    int b0 = 0, b1 = 0;
#pragma unroll
    for (int e = 0; e < NEXP; e++) {
        float v = logits[t * NEXP + e];
        if (v > best)        { second = best; b1 = b0; best = v; b0 = e; }
        else if (v > second) { second = v; b1 = e; }
    }
    float w0 = 1.0f / (1.0f + expf(second - best));
    g_tok_e[t][0] = b0;  g_tok_e[t][1] = b1;
    g_tok_w[t][0] = w0;  g_tok_w[t][1] = 1.0f - w0;
    atomicAdd(&g_counts[b0], 1);
    atomicAdd(&g_counts[b1], 1);
}

__global__ void k_prep() {
    if (threadIdx.x != 0 || blockIdx.x != 0) return;
    int off = 0, nt = 0;
    for (int e = 0; e < NEXP; e++) {
        int c = g_counts[e];
        g_cursor[e] = off;
        for (int r = 0; r < c; r += BM) {
            g_tile_e[nt]    = e;
            g_tile_row0[nt] = off + r;
            g_tile_m[nt]    = min(BM, c - r);
            nt++;
        }
        off += c;
    }
    g_ntiles = nt;
}

__global__ void k_scatter() {
    int t = blockIdx.x * blockDim.x + threadIdx.x;
    if (t >= NTOK) return;
#pragma unroll
    for (int k = 0; k < 2; k++) {
        int e = g_tok_e[t][k];
        int p = atomicAdd(&g_cursor[e], 1);
        g_bin_tok[p] = t;
        g_bin_w[p]   = g_tok_w[t][k];
    }
}

__global__ void k_zero(float* __restrict__ out) {
    int i = blockIdx.x * blockDim.x + threadIdx.x;
    if (i < (NTOK * HDIM) / 4) ((float4*)out)[i] = make_float4(0.f, 0.f, 0.f, 0.f);
}

// =====================================================================
// GEMM1 (FP16 mma.sync): h = silu(X@W1^T) * (X@W3^T)
// block 128(M) x 128(N), BK=32 halfs, 8 warps 2(M)x4(N), warp tile 64x32.
// smem: s_tok[512B] | A[2][10240] | B1[2][10240] | B3[2][10240]
// =====================================================================
#define G1_OFF_A   1024
#define G1_OFF_B1  (G1_OFF_A  + 2*TILE_B)
#define G1_OFF_B3  (G1_OFF_B1 + 2*TILE_B)
#define G1_SMEM    (G1_OFF_B3 + 2*TILE_B)   // 62464

__global__ void __launch_bounds__(256)
k_gemm1(const float* __restrict__ X,
        const float* __restrict__ W1,
        const float* __restrict__ W3) {
    if ((int)blockIdx.y >= g_ntiles) return;
    int te   = g_tile_e[blockIdx.y];
    int row0 = g_tile_row0[blockIdx.y];
    int mcnt = g_tile_m[blockIdx.y];
    int nb   = blockIdx.x * 128;

    extern __shared__ __align__(16) char smem[];
    int* s_tok = (int*)smem;
    __half* sA  = (__half*)(smem + G1_OFF_A);
    __half* sB1 = (__half*)(smem + G1_OFF_B1);
    __half* sB3 = (__half*)(smem + G1_OFF_B3);

    int tid = threadIdx.x;
    if (tid < BM) s_tok[tid] = (tid < mcnt) ? g_bin_tok[row0 + tid] : 0;
    __syncthreads();

    const float* W1e = W1 + (size_t)te * IDIM * HDIM;
    const float* W3e = W3 + (size_t)te * IDIM * HDIM;

    // loader mapping: c4 = k-quad (0..7 -> k offset c4*4), r0 = row base (0..31), rows r0+32j
    int c4 = tid & 7, r0 = tid >> 3;
    const float* apg[4];
    const float* b1g[4];
    const float* b3g[4];
#pragma unroll
    for (int j = 0; j < 4; j++) {
        apg[j] = X   + (size_t)s_tok[r0 + 32 * j] * HDIM + c4 * 4;
        b1g[j] = W1e + (size_t)(nb + r0 + 32 * j) * HDIM + c4 * 4;
        b3g[j] = W3e + (size_t)(nb + r0 + 32 * j) * HDIM + c4 * 4;
    }
    int sts_off = r0 * STRH + c4 * 4;   // half index within tile; +32 rows = +32*STRH

    // warp/lane mapping
    int warpId = tid >> 5, lane = tid & 31;
    int wm = (warpId & 1) * 64;
    int wn = (warpId >> 1) * 32;
    int fr = lane >> 2, fc = lane & 3;

    float acc1[4][4][4], acc3[4][4][4];
#pragma unroll
    for (int i = 0; i < 4; i++)
#pragma unroll
        for (int j = 0; j < 4; j++)
#pragma unroll
            for (int k = 0; k < 4; k++) { acc1[i][j][k] = 0.f; acc3[i][j][k] = 0.f; }

    float4 pa[4], p1[4], p3[4];
#pragma unroll
    for (int j = 0; j < 4; j++) {
        pa[j] = *(const float4*)(apg[j]);
        p1[j] = *(const float4*)(b1g[j]);
        p3[j] = *(const float4*)(b3g[j]);
    }
    // fill stage 0
#pragma unroll
    for (int j = 0; j < 4; j++) {
        *(uint2*)&sA [sts_off + j * 32 * STRH] = f4_to_h4(pa[j]);
        *(uint2*)&sB1[sts_off + j * 32 * STRH] = f4_to_h4(p1[j]);
        *(uint2*)&sB3[sts_off + j * 32 * STRH] = f4_to_h4(p3[j]);
    }
    __syncthreads();

    const int NIT = HDIM / BK;   // 32
    int buf = 0;
    for (int it = 0; it < NIT; it++) {
        if (it + 1 < NIT) {
            int kt = (it + 1) * BK;
#pragma unroll
            for (int j = 0; j < 4; j++) {
                pa[j] = *(const float4*)(apg[j] + kt);
                p1[j] = *(const float4*)(b1g[j] + kt);
                p3[j] = *(const float4*)(b3g[j] + kt);
            }
        }
        const __half* A  = sA  + buf * (BM * STRH);
        const __half* B1 = sB1 + buf * (BM * STRH);
        const __half* B3 = sB3 + buf * (BM * STRH);
#pragma unroll
        for (int kk = 0; kk < BK; kk += 16) {
            uint32_t a[4][4];
#pragma unroll
            for (int mt = 0; mt < 4; mt++) {
                const __half* ab = A + (wm + mt * 16 + fr) * STRH + kk + 2 * fc;
                a[mt][0] = *(const uint32_t*)(ab);
                a[mt][1] = *(const uint32_t*)(ab + 8 * STRH);
                a[mt][2] = *(const uint32_t*)(ab + 8);
                a[mt][3] = *(const uint32_t*)(ab + 8 * STRH + 8);
            }
#pragma unroll
            for (int nt = 0; nt < 4; nt++) {
                const __half* bb1 = B1 + (wn + nt * 8 + fr) * STRH + kk + 2 * fc;
                const __half* bb3 = B3 + (wn + nt * 8 + fr) * STRH + kk + 2 * fc;
                uint32_t b1f[2], b3f[2];
                b1f[0] = *(const uint32_t*)(bb1); b1f[1] = *(const uint32_t*)(bb1 + 8);
                b3f[0] = *(const uint32_t*)(bb3); b3f[1] = *(const uint32_t*)(bb3 + 8);
#pragma unroll
                for (int mt = 0; mt < 4; mt++) {
                    mma_f16(acc1[mt][nt], a[mt], b1f);
                    mma_f16(acc3[mt][nt], a[mt], b3f);
                }
            }
        }
        if (it + 1 < NIT) {
            __half* A2  = sA  + (buf ^ 1) * (BM * STRH);
            __half* B12 = sB1 + (buf ^ 1) * (BM * STRH);
            __half* B32 = sB3 + (buf ^ 1) * (BM * STRH);
            __syncthreads();
#pragma unroll
            for (int j = 0; j < 4; j++) {
                *(uint2*)&A2 [sts_off + j * 32 * STRH] = f4_to_h4(pa[j]);
                *(uint2*)&B12[sts_off + j * 32 * STRH] = f4_to_h4(p1[j]);
                *(uint2*)&B32[sts_off + j * 32 * STRH] = f4_to_h4(p3[j]);
            }
            __syncthreads();
        }
        buf ^= 1;
    }

    // epilogue: h = silu(c1)*c3 -> g_h (fp16)
#pragma unroll
    for (int mt = 0; mt < 4; mt++) {
        int m_lo = wm + mt * 16 + fr;
        int m_hi = m_lo + 8;
#pragma unroll
        for (int nt = 0; nt < 4; nt++) {
            int col = nb + wn + nt * 8 + fc * 2;
            if (m_lo < mcnt) {
                float c0 = acc1[mt][nt][0], c1 = acc1[mt][nt][1];
                float h0 = c0 / (1.0f + expf(-c0)) * acc3[mt][nt][0];
                float h1 = c1 / (1.0f + expf(-c1)) * acc3[mt][nt][1];
                __half2 hv = __floats2half2_rn(h0, h1);
                *(__half2*)&g_h[(size_t)(row0 + m_lo) * IDIM + col] = hv;
            }
            if (m_hi < mcnt) {
                float c2 = acc1[mt][nt][2], c3 = acc1[mt][nt][3];
                float h2 = c2 / (1.0f + expf(-c2)) * acc3[mt][nt][2];
                float h3 = c3 / (1.0f + expf(-c3)) * acc3[mt][nt][3];
                __half2 hv = __floats2half2_rn(h2, h3);
                *(__half2*)&g_h[(size_t)(row0 + m_hi) * IDIM + col] = hv;
            }
        }
    }
}

// =====================================================================
// GEMM2 (FP16 mma.sync): out[tok] += w * (h @ W2^T)
// block 128 x 128, BK=32 halfs. A is already fp16 in g_h.
// smem: s_tok[512] s_w[512] | A[2][10240] | B[2][10240]
// =====================================================================
#define G2_OFF_A  1024
#define G2_OFF_B  (G2_OFF_A + 2*TILE_B)
#define G2_SMEM   (G2_OFF_B + 2*TILE_B)   // 41984

__global__ void __launch_bounds__(256)
k_gemm2(const float* __restrict__ W2, float* __restrict__ out) {
    if ((int)blockIdx.y >= g_ntiles) return;
    int te   = g_tile_e[blockIdx.y];
    int row0 = g_tile_row0[blockIdx.y];
    int mcnt = g_tile_m[blockIdx.y];
    int nb   = blockIdx.x * 128;

    extern __shared__ __align__(16) char smem[];
    int*   s_tok = (int*)smem;
    float* s_w   = (float*)(smem + 512);
    __half* sA = (__half*)(smem + G2_OFF_A);
    __half* sB = (__half*)(smem + G2_OFF_B);

    int tid = threadIdx.x;
    if (tid < BM) {
        s_tok[tid] = (tid < mcnt) ? g_bin_tok[row0 + tid] : 0;
        s_w[tid]   = (tid < mcnt) ? g_bin_w[row0 + tid] : 0.0f;
    }
    __syncthreads();

    const float* W2e = W2 + (size_t)te * HDIM * IDIM;

    // A loader (fp16 source): c2 = 16B chunk (0..3 -> 8 halfs), r = row (0..63), rows r, r+64
    int c2 = tid & 3, ar = tid >> 2;
    int r0e = (ar      < mcnt) ? ar      : 0;
    int r1e = (ar + 64 < mcnt) ? ar + 64 : 0;
    const __half* ag0 = g_h + (size_t)(row0 + r0e) * IDIM + c2 * 8;
    const __half* ag1 = g_h + (size_t)(row0 + r1e) * IDIM + c2 * 8;
    int sts_a = ar * STRH + c2 * 8;

    // B loader (fp32 source): c4 (0..7), r0 (0..31), rows r0+32j
    int c4 = tid & 7, br = tid >> 3;
    const float* bg[4];
#pragma unroll
    for (int j = 0; j < 4; j++)
        bg[j] = W2e + (size_t)(nb + br + 32 * j) * IDIM + c4 * 4;
    int sts_b = br * STRH + c4 * 4;

    int warpId = tid >> 5, lane = tid & 31;
    int wm = (warpId & 1) * 64;
    int wn = (warpId >> 1) * 32;
    int fr = lane >> 2, fc = lane & 3;

    float acc[4][4][4];
#pragma unroll
    for (int i = 0; i < 4; i++)
#pragma unroll
        for (int j = 0; j < 4; j++)
#pragma unroll
            for (int k = 0; k < 4; k++) acc[i][j][k] = 0.f;

    uint4 qa0, qa1;
    float4 pb[4];
    qa0 = *(const uint4*)(ag0);
    qa1 = *(const uint4*)(ag1);
#pragma unroll
    for (int j = 0; j < 4; j++) pb[j] = *(const float4*)(bg[j]);

    *(uint4*)&sA[sts_a]             = qa0;
    *(uint4*)&sA[sts_a + 64 * STRH] = qa1;
#pragma unroll
    for (int j = 0; j < 4; j++)
        *(uint2*)&sB[sts_b + j * 32 * STRH] = f4_to_h4(pb[j]);
    __syncthreads();

    const int NIT = IDIM / BK;   // 88
    int buf = 0;
    for (int it = 0; it < NIT; it++) {
        if (it + 1 < NIT) {
            int kt = (it + 1) * BK;
            qa0 = *(const uint4*)(ag0 + kt);
            qa1 = *(const uint4*)(ag1 + kt);
#pragma unroll
            for (int j = 0; j < 4; j++) pb[j] = *(const float4*)(bg[j] + kt);
        }
        const __half* A = sA + buf * (BM * STRH);
        const __half* B = sB + buf * (BM * STRH);
#pragma unroll
        for (int kk = 0; kk < BK; kk += 16) {
            uint32_t a[4][4];
#pragma unroll
            for (int mt = 0; mt < 4; mt++) {
                const __half* ab = A + (wm + mt * 16 + fr) * STRH + kk + 2 * fc;
                a[mt][0] = *(const uint32_t*)(ab);
                a[mt][1] = *(const uint32_t*)(ab + 8 * STRH);
                a[mt][2] = *(const uint32_t*)(ab + 8);
                a[mt][3] = *(const uint32_t*)(ab + 8 * STRH + 8);
            }
#pragma unroll
            for (int nt = 0; nt < 4; nt++) {
                const __half* bb = B + (wn + nt * 8 + fr) * STRH + kk + 2 * fc;
                uint32_t bf[2];
                bf[0] = *(const uint32_t*)(bb); bf[1] = *(const uint32_t*)(bb + 8);
#pragma unroll
                for (int mt = 0; mt < 4; mt++)
                    mma_f16(acc[mt][nt], a[mt], bf);
            }
        }
        if (it + 1 < NIT) {
            __half* A2 = sA + (buf ^ 1) * (BM * STRH);
            __half* B2 = sB + (buf ^ 1) * (BM * STRH);
            __syncthreads();
            *(uint4*)&A2[sts_a]             = qa0;
            *(uint4*)&A2[sts_a + 64 * STRH] = qa1;
#pragma unroll
            for (int j = 0; j < 4; j++)
                *(uint2*)&B2[sts_b + j * 32 * STRH] = f4_to_h4(pb[j]);
            __syncthreads();
        }
        buf ^= 1;
    }

    // epilogue: weighted atomic scatter to tokens
#pragma unroll
    for (int mt = 0; mt < 4; mt++) {
        int m_lo = wm + mt * 16 + fr;
        int m_hi = m_lo + 8;
#pragma unroll
        for (int nt = 0; nt < 4; nt++) {
            int col = nb + wn + nt * 8 + fc * 2;
            if (m_lo < mcnt) {
                int tok = s_tok[m_lo]; float w = s_w[m_lo];
                float* op = out + (size_t)tok * HDIM + col;
                atomicAdd(op,     acc[mt][nt][0] * w);
                atomicAdd(op + 1, acc[mt][nt][1] * w);
            }
            if (m_hi < mcnt) {
                int tok = s_tok[m_hi]; float w = s_w[m_hi];
                float* op = out + (size_t)tok * HDIM + col;
                atomicAdd(op,     acc[mt][nt][2] * w);
                atomicAdd(op + 1, acc[mt][nt][3] * w);
            }
        }
    }
}

// ---------------- launch ----------------
extern "C" void kernel_launch(void* const* d_in, const int* in_sizes, int n_in,
                              void* d_out, int out_size) {
    const float* X  = (const float*)d_in[0];  // [T,H]
    const float* RL = (const float*)d_in[1];  // [T,E]
    const float* W1 = (const float*)d_in[2];  // [E,I,H]
    const float* W3 = (const float*)d_in[3];  // [E,I,H]
    const float* W2 = (const float*)d_in[4];  // [E,H,I]
    float* out = (float*)d_out;               // [T,H]

    cudaFuncSetAttribute(k_gemm1, cudaFuncAttributeMaxDynamicSharedMemorySize, G1_SMEM);
    cudaFuncSetAttribute(k_gemm2, cudaFuncAttributeMaxDynamicSharedMemorySize, G2_SMEM);

    k_init<<<1, 32>>>();
    k_router<<<NTOK / 256, 256>>>(RL);
    k_prep<<<1, 1>>>();
    k_scatter<<<NTOK / 256, 256>>>();
    k_zero<<<(NTOK * HDIM / 4 + 255) / 256, 256>>>(out);

    dim3 g1(IDIM / 128, MAX_TILES);   // 22 x 136
    k_gemm1<<<g1, 256, G1_SMEM>>>(X, W1, W3);

    dim3 g2(HDIM / 128, MAX_TILES);   // 8 x 136
    k_gemm2<<<g2, 256, G2_SMEM>>>(W2, out);
}

// round 6
// speedup vs baseline: 6.8246x; 1.1401x over previous
#include <cuda_runtime.h>
#include <cuda_fp16.h>
#include <math.h>
#include <stdint.h>

#define NTOK 8192
#define NEXP 8
#define IDIM 2816
#define HDIM 1024
#define NROWS (2*NTOK)                 // 16384 routed rows
#define BM 128
#define BK 32                          // halfs of K per smem stage
#define STRH 40                        // smem row stride in halfs (80B) -> conflict-free frags
#define STAGE_B (BM * STRH * 2)        // 10240 bytes per tile stage
#define NSTAGE 4
#define MAX_TILES (NROWS/BM + NEXP)    // 136

// ---- device scratch ----
__device__ __half g_h[(size_t)NROWS * IDIM];            // 92 MB intermediate h (fp16)
__device__ __half g_xh[(size_t)NTOK * HDIM];            // 16 MB X in fp16
__device__ __half g_w1h[(size_t)NEXP * IDIM * HDIM];    // 46 MB
__device__ __half g_w3h[(size_t)NEXP * IDIM * HDIM];    // 46 MB
__device__ __half g_w2h[(size_t)NEXP * HDIM * IDIM];    // 46 MB
__device__ int   g_bin_tok[NROWS];
__device__ float g_bin_w[NROWS];
__device__ int   g_counts[NEXP];
__device__ int   g_cursor[NEXP];
__device__ int   g_tok_e[NTOK][2];
__device__ float g_tok_w[NTOK][2];
__device__ int   g_tile_e[MAX_TILES];
__device__ int   g_tile_row0[MAX_TILES];
__device__ int   g_tile_m[MAX_TILES];
__device__ int   g_ntiles;

// ---------------- helpers ----------------
__device__ __forceinline__ void mma_f16(float* c, const uint32_t* a, const uint32_t* b) {
    asm volatile(
        "mma.sync.aligned.m16n8k16.row.col.f32.f16.f16.f32 "
        "{%0,%1,%2,%3},{%4,%5,%6,%7},{%8,%9},{%0,%1,%2,%3};"
        : "+f"(c[0]), "+f"(c[1]), "+f"(c[2]), "+f"(c[3])
        : "r"(a[0]), "r"(a[1]), "r"(a[2]), "r"(a[3]), "r"(b[0]), "r"(b[1]));
}
__device__ __forceinline__ uint32_t smem_u32(const void* p) {
    uint32_t a;
    asm("{ .reg .u64 t; cvta.to.shared.u64 t, %1; cvt.u32.u64 %0, t; }" : "=r"(a) : "l"(p));
    return a;
}
__device__ __forceinline__ void cpa16(uint32_t dst, const void* src) {
    asm volatile("cp.async.cg.shared.global [%0], [%1], 16;" :: "r"(dst), "l"(src));
}
__device__ __forceinline__ void cpa_commit() {
    asm volatile("cp.async.commit_group;" ::: "memory");
}
__device__ __forceinline__ void cpa_wait2() {
    asm volatile("cp.async.wait_group 2;" ::: "memory");
}

// ---------------- small kernels ----------------
__global__ void k_init() {
    if (threadIdx.x < NEXP) g_counts[threadIdx.x] = 0;
}

__global__ void k_router(const float* __restrict__ logits) {
    int t = blockIdx.x * blockDim.x + threadIdx.x;
    if (t >= NTOK) return;
    float best = -INFINITY, second = -INFINITY;
    int b0 = 0, b1 = 0;
#pragma unroll
    for (int e = 0; e < NEXP; e++) {
        float v = logits[t * NEXP + e];
        if (v > best)        { second = best; b1 = b0; best = v; b0 = e; }
        else if (v > second) { second = v; b1 = e; }
    }
    float w0 = 1.0f / (1.0f + expf(second - best));
    g_tok_e[t][0] = b0;  g_tok_e[t][1] = b1;
    g_tok_w[t][0] = w0;  g_tok_w[t][1] = 1.0f - w0;
    atomicAdd(&g_counts[b0], 1);
    atomicAdd(&g_counts[b1], 1);
}

__global__ void k_prep() {
    if (threadIdx.x != 0 || blockIdx.x != 0) return;
    int off = 0, nt = 0;
    for (int e = 0; e < NEXP; e++) {
        int c = g_counts[e];
        g_cursor[e] = off;
        for (int r = 0; r < c; r += BM) {
            g_tile_e[nt]    = e;
            g_tile_row0[nt] = off + r;
            g_tile_m[nt]    = min(BM, c - r);
            nt++;
        }
        off += c;
    }
    g_ntiles = nt;
}

__global__ void k_scatter() {
    int t = blockIdx.x * blockDim.x + threadIdx.x;
    if (t >= NTOK) return;
#pragma unroll
    for (int k = 0; k < 2; k++) {
        int e = g_tok_e[t][k];
        int p = atomicAdd(&g_cursor[e], 1);
        g_bin_tok[p] = t;
        g_bin_w[p]   = g_tok_w[t][k];
    }
}

__global__ void k_zero(float* __restrict__ out) {
    int i = blockIdx.x * blockDim.x + threadIdx.x;
    if (i < (NTOK * HDIM) / 4) ((float4*)out)[i] = make_float4(0.f, 0.f, 0.f, 0.f);
}

// fp32 -> fp16 bulk convert (float4 -> 4x half), grid-stride
__global__ void k_cvt(const float* __restrict__ src, __half* __restrict__ dst, int n4) {
    int stride = gridDim.x * blockDim.x;
    for (int i = blockIdx.x * blockDim.x + threadIdx.x; i < n4; i += stride) {
        float4 v = ((const float4*)src)[i];
        __half2 lo = __floats2half2_rn(v.x, v.y);
        __half2 hi = __floats2half2_rn(v.z, v.w);
        uint2 u;
        u.x = *(uint32_t*)&lo;
        u.y = *(uint32_t*)&hi;
        ((uint2*)dst)[i] = u;
    }
}

// =====================================================================
// GEMM1 (FP16 mma.sync + cp.async 4-stage): h = silu(X@W1^T) * (X@W3^T)
// block 128(M) x 128(N), BK=32 halfs, 8 warps 2(M)x4(N), warp tile 64x32.
// smem: s_tok[1024B] | A[4][10240] | B1[4][10240] | B3[4][10240]
// =====================================================================
#define G1_OFF_A   1024
#define G1_OFF_B1  (G1_OFF_A  + NSTAGE*STAGE_B)
#define G1_OFF_B3  (G1_OFF_B1 + NSTAGE*STAGE_B)
#define G1_SMEM    (G1_OFF_B3 + NSTAGE*STAGE_B)   // 123904

__global__ void __launch_bounds__(256)
k_gemm1() {
    if ((int)blockIdx.y >= g_ntiles) return;
    int te   = g_tile_e[blockIdx.y];
    int row0 = g_tile_row0[blockIdx.y];
    int mcnt = g_tile_m[blockIdx.y];
    int nb   = blockIdx.x * 128;

    extern __shared__ __align__(16) char smem[];
    int* s_tok = (int*)smem;
    uint32_t sbase = smem_u32(smem);

    int tid = threadIdx.x;
    if (tid < BM) s_tok[tid] = (tid < mcnt) ? g_bin_tok[row0 + tid] : 0;
    __syncthreads();

    const __half* W1e = g_w1h + (size_t)te * IDIM * HDIM;
    const __half* W3e = g_w3h + (size_t)te * IDIM * HDIM;

    // loader mapping: c = 8-half chunk (0..3), r = row (0..63); rows r, r+64
    int c = tid & 3, r = tid >> 2;
    const __half* a0 = g_xh + (size_t)s_tok[r]      * HDIM + c * 8;
    const __half* a1 = g_xh + (size_t)s_tok[r + 64] * HDIM + c * 8;
    const __half* b10 = W1e + (size_t)(nb + r) * HDIM + c * 8;
    const __half* b30 = W3e + (size_t)(nb + r) * HDIM + c * 8;
    uint32_t so = (uint32_t)(r * 80 + c * 16);     // byte offset within stage
    const uint32_t ROWSTEP = 64 * 80;              // +64 rows
    const size_t BROWSTEP = (size_t)64 * HDIM;

    // warp/lane mapping
    int warpId = tid >> 5, lane = tid & 31;
    int wm = (warpId & 1) * 64;
    int wn = (warpId >> 1) * 32;
    int fr = lane >> 2, fc = lane & 3;

    float acc1[4][4][4], acc3[4][4][4];
#pragma unroll
    for (int i = 0; i < 4; i++)
#pragma unroll
        for (int j = 0; j < 4; j++)
#pragma unroll
            for (int k = 0; k < 4; k++) { acc1[i][j][k] = 0.f; acc3[i][j][k] = 0.f; }

    const int NIT = HDIM / BK;   // 32

    // prologue: stages 0..2
#pragma unroll
    for (int s = 0; s < NSTAGE - 1; s++) {
        int kt = s * BK;
        uint32_t sa = sbase + G1_OFF_A  + s * STAGE_B + so;
        uint32_t s1 = sbase + G1_OFF_B1 + s * STAGE_B + so;
        uint32_t s3 = sbase + G1_OFF_B3 + s * STAGE_B + so;
        cpa16(sa, a0 + kt);            cpa16(sa + ROWSTEP, a1 + kt);
        cpa16(s1, b10 + kt);           cpa16(s1 + ROWSTEP, b10 + BROWSTEP + kt);
        cpa16(s3, b30 + kt);           cpa16(s3 + ROWSTEP, b30 + BROWSTEP + kt);
        cpa_commit();
    }

    for (int it = 0; it < NIT; it++) {
        cpa_wait2();
        __syncthreads();
        int st = it & (NSTAGE - 1);
        const __half* A  = (const __half*)(smem + G1_OFF_A  + st * STAGE_B);
        const __half* B1 = (const __half*)(smem + G1_OFF_B1 + st * STAGE_B);
        const __half* B3 = (const __half*)(smem + G1_OFF_B3 + st * STAGE_B);
#pragma unroll
        for (int kk = 0; kk < BK; kk += 16) {
            uint32_t a[4][4];
#pragma unroll
            for (int mt = 0; mt < 4; mt++) {
                const __half* ab = A + (wm + mt * 16 + fr) * STRH + kk + 2 * fc;
                a[mt][0] = *(const uint32_t*)(ab);
                a[mt][1] = *(const uint32_t*)(ab + 8 * STRH);
                a[mt][2] = *(const uint32_t*)(ab + 8);
                a[mt][3] = *(const uint32_t*)(ab + 8 * STRH + 8);
            }
#pragma unroll
            for (int nt = 0; nt < 4; nt++) {
                const __half* bb1 = B1 + (wn + nt * 8 + fr) * STRH + kk + 2 * fc;
                const __half* bb3 = B3 + (wn + nt * 8 + fr) * STRH + kk + 2 * fc;
                uint32_t b1f[2], b3f[2];
                b1f[0] = *(const uint32_t*)(bb1); b1f[1] = *(const uint32_t*)(bb1 + 8);
                b3f[0] = *(const uint32_t*)(bb3); b3f[1] = *(const uint32_t*)(bb3 + 8);
#pragma unroll
                for (int mt = 0; mt < 4; mt++) {
                    mma_f16(acc1[mt][nt], a[mt], b1f);
                    mma_f16(acc3[mt][nt], a[mt], b3f);
                }
            }
        }
        if (it + NSTAGE - 1 < NIT) {
            int s = (it + NSTAGE - 1) & (NSTAGE - 1);
            int kt = (it + NSTAGE - 1) * BK;
            uint32_t sa = sbase + G1_OFF_A  + s * STAGE_B + so;
            uint32_t s1 = sbase + G1_OFF_B1 + s * STAGE_B + so;
            uint32_t s3 = sbase + G1_OFF_B3 + s * STAGE_B + so;
            cpa16(sa, a0 + kt);            cpa16(sa + ROWSTEP, a1 + kt);
            cpa16(s1, b10 + kt);           cpa16(s1 + ROWSTEP, b10 + BROWSTEP + kt);
            cpa16(s3, b30 + kt);           cpa16(s3 + ROWSTEP, b30 + BROWSTEP + kt);
        }
        cpa_commit();   // always commit to keep group numbering uniform
    }

    // epilogue: h = silu(c1)*c3 -> g_h (fp16)
#pragma unroll
    for (int mt = 0; mt < 4; mt++) {
        int m_lo = wm + mt * 16 + fr;
        int m_hi = m_lo + 8;
#pragma unroll
        for (int nt = 0; nt < 4; nt++) {
            int col = nb + wn + nt * 8 + fc * 2;
            if (m_lo < mcnt) {
                float c0 = acc1[mt][nt][0], c1 = acc1[mt][nt][1];
                float h0 = c0 / (1.0f + expf(-c0)) * acc3[mt][nt][0];
                float h1 = c1 / (1.0f + expf(-c1)) * acc3[mt][nt][1];
                *(__half2*)&g_h[(size_t)(row0 + m_lo) * IDIM + col] = __floats2half2_rn(h0, h1);
            }
            if (m_hi < mcnt) {
                float c2 = acc1[mt][nt][2], c3 = acc1[mt][nt][3];
                float h2 = c2 / (1.0f + expf(-c2)) * acc3[mt][nt][2];
                float h3 = c3 / (1.0f + expf(-c3)) * acc3[mt][nt][3];
                *(__half2*)&g_h[(size_t)(row0 + m_hi) * IDIM + col] = __floats2half2_rn(h2, h3);
            }
        }
    }
}

// =====================================================================
// GEMM2 (FP16 mma.sync + cp.async 4-stage): out[tok] += w * (h @ W2^T)
// smem: s_tok/s_w[1024B] | A[4][10240] | B[4][10240]
// =====================================================================
#define G2_OFF_A  1024
#define G2_OFF_B  (G2_OFF_A + NSTAGE*STAGE_B)
#define G2_SMEM   (G2_OFF_B + NSTAGE*STAGE_B)   // 82944

__global__ void __launch_bounds__(256)
k_gemm2(float* __restrict__ out) {
    if ((int)blockIdx.y >= g_ntiles) return;
    int te   = g_tile_e[blockIdx.y];
    int row0 = g_tile_row0[blockIdx.y];
    int mcnt = g_tile_m[blockIdx.y];
    int nb   = blockIdx.x * 128;

    extern __shared__ __align__(16) char smem[];
    int*   s_tok = (int*)smem;
    float* s_w   = (float*)(smem + 512);
    uint32_t sbase = smem_u32(smem);

    int tid = threadIdx.x;
    if (tid < BM) {
        s_tok[tid] = (tid < mcnt) ? g_bin_tok[row0 + tid] : 0;
        s_w[tid]   = (tid < mcnt) ? g_bin_w[row0 + tid] : 0.0f;
    }
    __syncthreads();

    const __half* W2e = g_w2h + (size_t)te * HDIM * IDIM;

    int c = tid & 3, r = tid >> 2;
    int r0e = (r      < mcnt) ? r      : 0;
    int r1e = (r + 64 < mcnt) ? r + 64 : 0;
    const __half* a0 = g_h + (size_t)(row0 + r0e) * IDIM + c * 8;
    const __half* a1 = g_h + (size_t)(row0 + r1e) * IDIM + c * 8;
    const __half* b0 = W2e + (size_t)(nb + r) * IDIM + c * 8;
    uint32_t so = (uint32_t)(r * 80 + c * 16);
    const uint32_t ROWSTEP = 64 * 80;
    const size_t BROWSTEP = (size_t)64 * IDIM;

    int warpId = tid >> 5, lane = tid & 31;
    int wm = (warpId & 1) * 64;
    int wn = (warpId >> 1) * 32;
    int fr = lane >> 2, fc = lane & 3;

    float acc[4][4][4];
#pragma unroll
    for (int i = 0; i < 4; i++)
#pragma unroll
        for (int j = 0; j < 4; j++)
#pragma unroll
            for (int k = 0; k < 4; k++) acc[i][j][k] = 0.f;

    const int NIT = IDIM / BK;   // 88

#pragma unroll
    for (int s = 0; s < NSTAGE - 1; s++) {
        int kt = s * BK;
        uint32_t sa = sbase + G2_OFF_A + s * STAGE_B + so;
        uint32_t sb = sbase + G2_OFF_B + s * STAGE_B + so;
        cpa16(sa, a0 + kt);  cpa16(sa + ROWSTEP, a1 + kt);
        cpa16(sb, b0 + kt);  cpa16(sb + ROWSTEP, b0 + BROWSTEP + kt);
        cpa_commit();
    }

    for (int it = 0; it < NIT; it++) {
        cpa_wait2();
        __syncthreads();
        int st = it & (NSTAGE - 1);
        const __half* A = (const __half*)(smem + G2_OFF_A + st * STAGE_B);
        const __half* B = (const __half*)(smem + G2_OFF_B + st * STAGE_B);
#pragma unroll
        for (int kk = 0; kk < BK; kk += 16) {
            uint32_t a[4][4];
#pragma unroll
            for (int mt = 0; mt < 4; mt++) {
                const __half* ab = A + (wm + mt * 16 + fr) * STRH + kk + 2 * fc;
                a[mt][0] = *(const uint32_t*)(ab);
                a[mt][1] = *(const uint32_t*)(ab + 8 * STRH);
                a[mt][2] = *(const uint32_t*)(ab + 8);
                a[mt][3] = *(const uint32_t*)(ab + 8 * STRH + 8);
            }
#pragma unroll
            for (int nt = 0; nt < 4; nt++) {
                const __half* bb = B + (wn + nt * 8 + fr) * STRH + kk + 2 * fc;
                uint32_t bf[2];
                bf[0] = *(const uint32_t*)(bb); bf[1] = *(const uint32_t*)(bb + 8);
#pragma unroll
                for (int mt = 0; mt < 4; mt++)
                    mma_f16(acc[mt][nt], a[mt], bf);
            }
        }
        if (it + NSTAGE - 1 < NIT) {
            int s = (it + NSTAGE - 1) & (NSTAGE - 1);
            int kt = (it + NSTAGE - 1) * BK;
            uint32_t sa = sbase + G2_OFF_A + s * STAGE_B + so;
            uint32_t sb = sbase + G2_OFF_B + s * STAGE_B + so;
            cpa16(sa, a0 + kt);  cpa16(sa + ROWSTEP, a1 + kt);
            cpa16(sb, b0 + kt);  cpa16(sb + ROWSTEP, b0 + BROWSTEP + kt);
        }
        cpa_commit();
    }

    // epilogue: weighted atomic scatter to tokens
#pragma unroll
    for (int mt = 0; mt < 4; mt++) {
        int m_lo = wm + mt * 16 + fr;
        int m_hi = m_lo + 8;
#pragma unroll
        for (int nt = 0; nt < 4; nt++) {
            int col = nb + wn + nt * 8 + fc * 2;
            if (m_lo < mcnt) {
                int tok = s_tok[m_lo]; float w = s_w[m_lo];
                float* op = out + (size_t)tok * HDIM + col;
                atomicAdd(op,     acc[mt][nt][0] * w);
                atomicAdd(op + 1, acc[mt][nt][1] * w);
            }
            if (m_hi < mcnt) {
                int tok = s_tok[m_hi]; float w = s_w[m_hi];
                float* op = out + (size_t)tok * HDIM + col;
                atomicAdd(op,     acc[mt][nt][2] * w);
                atomicAdd(op + 1, acc[mt][nt][3] * w);
            }
        }
    }
}

// ---------------- launch ----------------
extern "C" void kernel_launch(void* const* d_in, const int* in_sizes, int n_in,
                              void* d_out, int out_size) {
    const float* X  = (const float*)d_in[0];  // [T,H]
    const float* RL = (const float*)d_in[1];  // [T,E]
    const float* W1 = (const float*)d_in[2];  // [E,I,H]
    const float* W3 = (const float*)d_in[3];  // [E,I,H]
    const float* W2 = (const float*)d_in[4];  // [E,H,I]
    float* out = (float*)d_out;               // [T,H]

    cudaFuncSetAttribute(k_gemm1, cudaFuncAttributeMaxDynamicSharedMemorySize, G1_SMEM);
    cudaFuncSetAttribute(k_gemm2, cudaFuncAttributeMaxDynamicSharedMemorySize, G2_SMEM);

    k_init<<<1, 32>>>();
    k_router<<<NTOK / 256, 256>>>(RL);
    k_prep<<<1, 1>>>();
    k_scatter<<<NTOK / 256, 256>>>();

    // fp32 -> fp16 conversions
    __half* xh, *w1h, *w3h, *w2h;
    cudaGetSymbolAddress((void**)&xh,  g_xh);
    cudaGetSymbolAddress((void**)&w1h, g_w1h);
    cudaGetSymbolAddress((void**)&w3h, g_w3h);
    cudaGetSymbolAddress((void**)&w2h, g_w2h);
    int nX = NTOK * HDIM / 4;
    int nW = NEXP * IDIM * HDIM / 4;
    k_cvt<<<1024, 256>>>(X,  xh,  nX);
    k_cvt<<<2048, 256>>>(W1, w1h, nW);
    k_cvt<<<2048, 256>>>(W3, w3h, nW);
    k_cvt<<<2048, 256>>>(W2, w2h, nW);

    k_zero<<<(NTOK * HDIM / 4 + 255) / 256, 256>>>(out);

    dim3 g1(IDIM / 128, MAX_TILES);   // 22 x 136
    k_gemm1<<<g1, 256, G1_SMEM>>>();

    dim3 g2(HDIM / 128, MAX_TILES);   // 8 x 136
    k_gemm2<<<g2, 256, G2_SMEM>>>(out);
}

// round 7
// speedup vs baseline: 7.0635x; 1.0350x over previous
#include <cuda_runtime.h>
#include <cuda_fp16.h>
#include <math.h>
#include <stdint.h>

#define NTOK 8192
#define NEXP 8
#define IDIM 2816
#define HDIM 1024
#define NROWS (2*NTOK)                 // 16384 routed rows
#define BM 128
#define BK 32                          // halfs of K per smem stage
#define STRH 40                        // smem row stride in halfs (80B)
#define STAGE_B (BM * STRH * 2)        // 10240 bytes per tile stage
#define NSTAGE 4
#define MAX_TILES (NROWS/BM + NEXP)    // 136

// ---- device scratch ----
__device__ __half g_h[(size_t)NROWS * IDIM];            // 92 MB intermediate h (fp16)
__device__ float  g_part[(size_t)NROWS * HDIM];         // 67 MB unweighted GEMM2 partials
__device__ __half g_xh[(size_t)NTOK * HDIM];            // 16 MB X in fp16
__device__ __half g_w1h[(size_t)NEXP * IDIM * HDIM];    // 46 MB
__device__ __half g_w3h[(size_t)NEXP * IDIM * HDIM];    // 46 MB
__device__ __half g_w2h[(size_t)NEXP * HDIM * IDIM];    // 46 MB
__device__ int   g_bin_tok[NROWS];
__device__ int   g_cursor[NEXP];
__device__ int   g_tok_e[NTOK][2];
__device__ float g_tok_w[NTOK][2];
__device__ int   g_pos[NTOK][2];
__device__ int   g_tile_e[MAX_TILES];
__device__ int   g_tile_row0[MAX_TILES];
__device__ int   g_tile_m[MAX_TILES];
__device__ int   g_ntiles;

// ---------------- helpers ----------------
__device__ __forceinline__ void mma_f16(float* c, const uint32_t* a, const uint32_t* b) {
    asm volatile(
        "mma.sync.aligned.m16n8k16.row.col.f32.f16.f16.f32 "
        "{%0,%1,%2,%3},{%4,%5,%6,%7},{%8,%9},{%0,%1,%2,%3};"
        : "+f"(c[0]), "+f"(c[1]), "+f"(c[2]), "+f"(c[3])
        : "r"(a[0]), "r"(a[1]), "r"(a[2]), "r"(a[3]), "r"(b[0]), "r"(b[1]));
}
__device__ __forceinline__ void ldsm4(uint32_t* r, uint32_t addr) {
    asm volatile("ldmatrix.sync.aligned.m8n8.x4.shared.b16 {%0,%1,%2,%3}, [%4];"
        : "=r"(r[0]), "=r"(r[1]), "=r"(r[2]), "=r"(r[3]) : "r"(addr));
}
__device__ __forceinline__ uint32_t smem_u32(const void* p) {
    uint32_t a;
    asm("{ .reg .u64 t; cvta.to.shared.u64 t, %1; cvt.u32.u64 %0, t; }" : "=r"(a) : "l"(p));
    return a;
}
__device__ __forceinline__ void cpa16(uint32_t dst, const void* src) {
    asm volatile("cp.async.cg.shared.global [%0], [%1], 16;" :: "r"(dst), "l"(src));
}
__device__ __forceinline__ void cpa_commit() {
    asm volatile("cp.async.commit_group;" ::: "memory");
}
__device__ __forceinline__ void cpa_wait2() {
    asm volatile("cp.async.wait_group 2;" ::: "memory");
}

// ---------------- small kernels ----------------
// fp32 -> fp16 bulk convert
__global__ void k_cvtX(const float* __restrict__ src, __half* __restrict__ dst, int n4) {
    int stride = gridDim.x * blockDim.x;
    for (int i = blockIdx.x * blockDim.x + threadIdx.x; i < n4; i += stride) {
        float4 v = ((const float4*)src)[i];
        __half2 lo = __floats2half2_rn(v.x, v.y);
        __half2 hi = __floats2half2_rn(v.z, v.w);
        uint2 u; u.x = *(uint32_t*)&lo; u.y = *(uint32_t*)&hi;
        ((uint2*)dst)[i] = u;
    }
}
__global__ void k_cvtW(const float* __restrict__ w1, const float* __restrict__ w3,
                       const float* __restrict__ w2) {
    const int n4 = NEXP * IDIM * HDIM / 4;
    int stride = gridDim.x * blockDim.x;
    for (int i = blockIdx.x * blockDim.x + threadIdx.x; i < n4; i += stride) {
        float4 v;
        uint2 u;
        __half2 lo, hi;
        v = ((const float4*)w1)[i];
        lo = __floats2half2_rn(v.x, v.y); hi = __floats2half2_rn(v.z, v.w);
        u.x = *(uint32_t*)&lo; u.y = *(uint32_t*)&hi;
        ((uint2*)g_w1h)[i] = u;
        v = ((const float4*)w3)[i];
        lo = __floats2half2_rn(v.x, v.y); hi = __floats2half2_rn(v.z, v.w);
        u.x = *(uint32_t*)&lo; u.y = *(uint32_t*)&hi;
        ((uint2*)g_w3h)[i] = u;
        v = ((const float4*)w2)[i];
        lo = __floats2half2_rn(v.x, v.y); hi = __floats2half2_rn(v.z, v.w);
        u.x = *(uint32_t*)&lo; u.y = *(uint32_t*)&hi;
        ((uint2*)g_w2h)[i] = u;
    }
}

__global__ void k_router(const float* __restrict__ logits) {
    int t = blockIdx.x * blockDim.x + threadIdx.x;
    if (t >= NTOK) return;
    float best = -INFINITY, second = -INFINITY;
    int b0 = 0, b1 = 0;
#pragma unroll
    for (int e = 0; e < NEXP; e++) {
        float v = logits[t * NEXP + e];
        if (v > best)        { second = best; b1 = b0; best = v; b0 = e; }
        else if (v > second) { second = v; b1 = e; }
    }
    float w0 = 1.0f / (1.0f + expf(second - best));
    g_tok_e[t][0] = b0;  g_tok_e[t][1] = b1;
    g_tok_w[t][0] = w0;  g_tok_w[t][1] = 1.0f - w0;
}

// histogram + prefix + tile map (1 block, 256 threads)
__global__ void k_prep() {
    __shared__ int hc[NEXP];
    int tid = threadIdx.x;
    if (tid < NEXP) hc[tid] = 0;
    __syncthreads();
    for (int t = tid; t < NTOK; t += 256) {
        atomicAdd(&hc[g_tok_e[t][0]], 1);
        atomicAdd(&hc[g_tok_e[t][1]], 1);
    }
    __syncthreads();
    if (tid == 0) {
        int off = 0, nt = 0;
        for (int e = 0; e < NEXP; e++) {
            int c = hc[e];
            g_cursor[e] = off;
            for (int r = 0; r < c; r += BM) {
                g_tile_e[nt]    = e;
                g_tile_row0[nt] = off + r;
                g_tile_m[nt]    = min(BM, c - r);
                nt++;
            }
            off += c;
        }
        g_ntiles = nt;
    }
}

__global__ void k_scatter() {
    int t = blockIdx.x * blockDim.x + threadIdx.x;
    if (t >= NTOK) return;
#pragma unroll
    for (int k = 0; k < 2; k++) {
        int e = g_tok_e[t][k];
        int p = atomicAdd(&g_cursor[e], 1);
        g_bin_tok[p] = t;
        g_pos[t][k]  = p;
    }
}

// out[t] = w0 * part[p0] + w1 * part[p1]
__global__ void k_gather(float* __restrict__ out) {
    const int n4 = NTOK * HDIM / 4;
    int stride = gridDim.x * blockDim.x;
    for (int i = blockIdx.x * blockDim.x + threadIdx.x; i < n4; i += stride) {
        int t = i >> 8;              // HDIM/4 = 256
        int c = i & 255;
        int p0 = g_pos[t][0], p1 = g_pos[t][1];
        float w0 = g_tok_w[t][0], w1 = g_tok_w[t][1];
        float4 a = ((const float4*)g_part)[(size_t)p0 * 256 + c];
        float4 b = ((const float4*)g_part)[(size_t)p1 * 256 + c];
        float4 o;
        o.x = w0 * a.x + w1 * b.x;
        o.y = w0 * a.y + w1 * b.y;
        o.z = w0 * a.z + w1 * b.z;
        o.w = w0 * a.w + w1 * b.w;
        ((float4*)out)[i] = o;
    }
}

// =====================================================================
// GEMM1 (FP16 mma.sync + ldmatrix + cp.async 4-stage): h = silu(X@W1^T)*(X@W3^T)
// block 128(M) x 128(N), BK=32 halfs, 8 warps 2(M)x4(N), warp tile 64x32.
// =====================================================================
#define G1_OFF_A   1024
#define G1_OFF_B1  (G1_OFF_A  + NSTAGE*STAGE_B)
#define G1_OFF_B3  (G1_OFF_B1 + NSTAGE*STAGE_B)
#define G1_SMEM    (G1_OFF_B3 + NSTAGE*STAGE_B)   // 123904

__global__ void __launch_bounds__(256, 1)
k_gemm1() {
    if ((int)blockIdx.y >= g_ntiles) return;
    int te   = g_tile_e[blockIdx.y];
    int row0 = g_tile_row0[blockIdx.y];
    int mcnt = g_tile_m[blockIdx.y];
    int nb   = blockIdx.x * 128;

    extern __shared__ __align__(16) char smem[];
    int* s_tok = (int*)smem;
    uint32_t sbase = smem_u32(smem);

    int tid = threadIdx.x;
    if (tid < BM) s_tok[tid] = (tid < mcnt) ? g_bin_tok[row0 + tid] : 0;
    __syncthreads();

    const __half* W1e = g_w1h + (size_t)te * IDIM * HDIM;
    const __half* W3e = g_w3h + (size_t)te * IDIM * HDIM;

    // cp.async loader mapping: c = 8-half chunk (0..3), r = row (0..63); rows r, r+64
    int c = tid & 3, r = tid >> 2;
    const __half* a0 = g_xh + (size_t)s_tok[r]      * HDIM + c * 8;
    const __half* a1 = g_xh + (size_t)s_tok[r + 64] * HDIM + c * 8;
    const __half* b10 = W1e + (size_t)(nb + r) * HDIM + c * 8;
    const __half* b30 = W3e + (size_t)(nb + r) * HDIM + c * 8;
    uint32_t so = (uint32_t)(r * 80 + c * 16);
    const uint32_t ROWSTEP = 64 * 80;
    const size_t BROWSTEP = (size_t)64 * HDIM;

    // warp/lane mapping
    int warpId = tid >> 5, lane = tid & 31;
    int wm = (warpId & 1) * 64;
    int wn = (warpId >> 1) * 32;
    int fr = lane >> 2, fc = lane & 3;

    // ldmatrix per-lane offsets (byte offsets within a stage)
    uint32_t a_lo = (uint32_t)((wm + (lane & 15)) * 80 + (lane >> 4) * 16);
    uint32_t b_lo = (uint32_t)((wn + (lane & 7) + ((lane >> 4) & 1) * 8) * 80 + ((lane >> 3) & 1) * 16);

    float acc1[4][4][4], acc3[4][4][4];
#pragma unroll
    for (int i = 0; i < 4; i++)
#pragma unroll
        for (int j = 0; j < 4; j++)
#pragma unroll
            for (int k = 0; k < 4; k++) { acc1[i][j][k] = 0.f; acc3[i][j][k] = 0.f; }

    const int NIT = HDIM / BK;   // 32

    // prologue: stages 0..2
#pragma unroll
    for (int s = 0; s < NSTAGE - 1; s++) {
        int kt = s * BK;
        uint32_t sa = sbase + G1_OFF_A  + s * STAGE_B + so;
        uint32_t s1 = sbase + G1_OFF_B1 + s * STAGE_B + so;
        uint32_t s3 = sbase + G1_OFF_B3 + s * STAGE_B + so;
        cpa16(sa, a0 + kt);   cpa16(sa + ROWSTEP, a1 + kt);
        cpa16(s1, b10 + kt);  cpa16(s1 + ROWSTEP, b10 + BROWSTEP + kt);
        cpa16(s3, b30 + kt);  cpa16(s3 + ROWSTEP, b30 + BROWSTEP + kt);
        cpa_commit();
    }

    for (int it = 0; it < NIT; it++) {
        cpa_wait2();
        __syncthreads();
        // issue next stage FIRST (full iteration of overlap)
        if (it + NSTAGE - 1 < NIT) {
            int s = (it + NSTAGE - 1) & (NSTAGE - 1);
            int kt = (it + NSTAGE - 1) * BK;
            uint32_t sa = sbase + G1_OFF_A  + s * STAGE_B + so;
            uint32_t s1 = sbase + G1_OFF_B1 + s * STAGE_B + so;
            uint32_t s3 = sbase + G1_OFF_B3 + s * STAGE_B + so;
            cpa16(sa, a0 + kt);   cpa16(sa + ROWSTEP, a1 + kt);
            cpa16(s1, b10 + kt);  cpa16(s1 + ROWSTEP, b10 + BROWSTEP + kt);
            cpa16(s3, b30 + kt);  cpa16(s3 + ROWSTEP, b30 + BROWSTEP + kt);
        }
        cpa_commit();

        int st = it & (NSTAGE - 1);
        uint32_t abase = sbase + G1_OFF_A  + st * STAGE_B + a_lo;
        uint32_t b1b   = sbase + G1_OFF_B1 + st * STAGE_B + b_lo;
        uint32_t b3b   = sbase + G1_OFF_B3 + st * STAGE_B + b_lo;
#pragma unroll
        for (int kk = 0; kk < BK; kk += 16) {
            uint32_t a[4][4];
#pragma unroll
            for (int mt = 0; mt < 4; mt++)
                ldsm4(a[mt], abase + mt * 16 * 80 + kk * 2);
            uint32_t bf1[2][4], bf3[2][4];
#pragma unroll
            for (int p = 0; p < 2; p++) {
                ldsm4(bf1[p], b1b + p * 16 * 80 + kk * 2);
                ldsm4(bf3[p], b3b + p * 16 * 80 + kk * 2);
            }
#pragma unroll
            for (int p = 0; p < 2; p++)
#pragma unroll
                for (int mt = 0; mt < 4; mt++) {
                    mma_f16(acc1[mt][2*p],   a[mt], &bf1[p][0]);
                    mma_f16(acc1[mt][2*p+1], a[mt], &bf1[p][2]);
                    mma_f16(acc3[mt][2*p],   a[mt], &bf3[p][0]);
                    mma_f16(acc3[mt][2*p+1], a[mt], &bf3[p][2]);
                }
        }
    }

    // epilogue: h = silu(c1)*c3 -> g_h (fp16)
#pragma unroll
    for (int mt = 0; mt < 4; mt++) {
        int m_lo = wm + mt * 16 + fr;
        int m_hi = m_lo + 8;
#pragma unroll
        for (int nt = 0; nt < 4; nt++) {
            int col = nb + wn + nt * 8 + fc * 2;
            if (m_lo < mcnt) {
                float c0 = acc1[mt][nt][0], c1 = acc1[mt][nt][1];
                float h0 = c0 / (1.0f + expf(-c0)) * acc3[mt][nt][0];
                float h1 = c1 / (1.0f + expf(-c1)) * acc3[mt][nt][1];
                *(__half2*)&g_h[(size_t)(row0 + m_lo) * IDIM + col] = __floats2half2_rn(h0, h1);
            }
            if (m_hi < mcnt) {
                float c2 = acc1[mt][nt][2], c3 = acc1[mt][nt][3];
                float h2 = c2 / (1.0f + expf(-c2)) * acc3[mt][nt][2];
                float h3 = c3 / (1.0f + expf(-c3)) * acc3[mt][nt][3];
                *(__half2*)&g_h[(size_t)(row0 + m_hi) * IDIM + col] = __floats2half2_rn(h2, h3);
            }
        }
    }
}

// =====================================================================
// GEMM2 (FP16 mma.sync + ldmatrix + cp.async 4-stage): part = h @ W2^T
// =====================================================================
#define G2_OFF_A  1024
#define G2_OFF_B  (G2_OFF_A + NSTAGE*STAGE_B)
#define G2_SMEM   (G2_OFF_B + NSTAGE*STAGE_B)   // 82944

__global__ void __launch_bounds__(256, 1)
k_gemm2() {
    if ((int)blockIdx.y >= g_ntiles) return;
    int te   = g_tile_e[blockIdx.y];
    int row0 = g_tile_row0[blockIdx.y];
    int mcnt = g_tile_m[blockIdx.y];
    int nb   = blockIdx.x * 128;

    extern __shared__ __align__(16) char smem[];
    uint32_t sbase = smem_u32(smem);
    int tid = threadIdx.x;

    const __half* W2e = g_w2h + (size_t)te * HDIM * IDIM;

    int c = tid & 3, r = tid >> 2;
    int r0e = (r      < mcnt) ? r      : 0;
    int r1e = (r + 64 < mcnt) ? r + 64 : 0;
    const __half* a0 = g_h + (size_t)(row0 + r0e) * IDIM + c * 8;
    const __half* a1 = g_h + (size_t)(row0 + r1e) * IDIM + c * 8;
    const __half* b0 = W2e + (size_t)(nb + r) * IDIM + c * 8;
    uint32_t so = (uint32_t)(r * 80 + c * 16);
    const uint32_t ROWSTEP = 64 * 80;
    const size_t BROWSTEP = (size_t)64 * IDIM;

    int warpId = tid >> 5, lane = tid & 31;
    int wm = (warpId & 1) * 64;
    int wn = (warpId >> 1) * 32;
    int fr = lane >> 2, fc = lane & 3;

    uint32_t a_lo = (uint32_t)((wm + (lane & 15)) * 80 + (lane >> 4) * 16);
    uint32_t b_lo = (uint32_t)((wn + (lane & 7) + ((lane >> 4) & 1) * 8) * 80 + ((lane >> 3) & 1) * 16);

    float acc[4][4][4];
#pragma unroll
    for (int i = 0; i < 4; i++)
#pragma unroll
        for (int j = 0; j < 4; j++)
#pragma unroll
            for (int k = 0; k < 4; k++) acc[i][j][k] = 0.f;

    const int NIT = IDIM / BK;   // 88

#pragma unroll
    for (int s = 0; s < NSTAGE - 1; s++) {
        int kt = s * BK;
        uint32_t sa = sbase + G2_OFF_A + s * STAGE_B + so;
        uint32_t sb = sbase + G2_OFF_B + s * STAGE_B + so;
        cpa16(sa, a0 + kt);  cpa16(sa + ROWSTEP, a1 + kt);
        cpa16(sb, b0 + kt);  cpa16(sb + ROWSTEP, b0 + BROWSTEP + kt);
        cpa_commit();
    }

    for (int it = 0; it < NIT; it++) {
        cpa_wait2();
        __syncthreads();
        if (it + NSTAGE - 1 < NIT) {
            int s = (it + NSTAGE - 1) & (NSTAGE - 1);
            int kt = (it + NSTAGE - 1) * BK;
            uint32_t sa = sbase + G2_OFF_A + s * STAGE_B + so;
            uint32_t sb = sbase + G2_OFF_B + s * STAGE_B + so;
            cpa16(sa, a0 + kt);  cpa16(sa + ROWSTEP, a1 + kt);
            cpa16(sb, b0 + kt);  cpa16(sb + ROWSTEP, b0 + BROWSTEP + kt);
        }
        cpa_commit();

        int st = it & (NSTAGE - 1);
        uint32_t abase = sbase + G2_OFF_A + st * STAGE_B + a_lo;
        uint32_t bbase = sbase + G2_OFF_B + st * STAGE_B + b_lo;
#pragma unroll
        for (int kk = 0; kk < BK; kk += 16) {
            uint32_t a[4][4];
#pragma unroll
            for (int mt = 0; mt < 4; mt++)
                ldsm4(a[mt], abase + mt * 16 * 80 + kk * 2);
            uint32_t bf[2][4];
#pragma unroll
            for (int p = 0; p < 2; p++)
                ldsm4(bf[p], bbase + p * 16 * 80 + kk * 2);
#pragma unroll
            for (int p = 0; p < 2; p++)
#pragma unroll
                for (int mt = 0; mt < 4; mt++) {
                    mma_f16(acc[mt][2*p],   a[mt], &bf[p][0]);
                    mma_f16(acc[mt][2*p+1], a[mt], &bf[p][2]);
                }
        }
    }

    // epilogue: plain stores of unweighted partials to contiguous bin rows
#pragma unroll
    for (int mt = 0; mt < 4; mt++) {
        int m_lo = wm + mt * 16 + fr;
        int m_hi = m_lo + 8;
#pragma unroll
        for (int nt = 0; nt < 4; nt++) {
            int col = nb + wn + nt * 8 + fc * 2;
            if (m_lo < mcnt) {
                float2 v = make_float2(acc[mt][nt][0], acc[mt][nt][1]);
                *(float2*)&g_part[(size_t)(row0 + m_lo) * HDIM + col] = v;
            }
            if (m_hi < mcnt) {
                float2 v = make_float2(acc[mt][nt][2], acc[mt][nt][3]);
                *(float2*)&g_part[(size_t)(row0 + m_hi) * HDIM + col] = v;
            }
        }
    }
}

// ---------------- launch ----------------
extern "C" void kernel_launch(void* const* d_in, const int* in_sizes, int n_in,
                              void* d_out, int out_size) {
    const float* X  = (const float*)d_in[0];  // [T,H]
    const float* RL = (const float*)d_in[1];  // [T,E]
    const float* W1 = (const float*)d_in[2];  // [E,I,H]
    const float* W3 = (const float*)d_in[3];  // [E,I,H]
    const float* W2 = (const float*)d_in[4];  // [E,H,I]
    float* out = (float*)d_out;               // [T,H]

    cudaFuncSetAttribute(k_gemm1, cudaFuncAttributeMaxDynamicSharedMemorySize, G1_SMEM);
    cudaFuncSetAttribute(k_gemm2, cudaFuncAttributeMaxDynamicSharedMemorySize, G2_SMEM);

    __half* xh;
    cudaGetSymbolAddress((void**)&xh, g_xh);

    k_cvtX<<<1024, 256>>>(X, xh, NTOK * HDIM / 4);   // 1
    k_cvtW<<<2048, 256>>>(W1, W3, W2);               // 2
    k_router<<<NTOK / 256, 256>>>(RL);               // 3
    k_prep<<<1, 256>>>();                            // 4
    k_scatter<<<NTOK / 256, 256>>>();                // 5

    dim3 g1(IDIM / 128, MAX_TILES);                  // 6: 22 x 136
    k_gemm1<<<g1, 256, G1_SMEM>>>();

    dim3 g2(HDIM / 128, MAX_TILES);                  // 7: 8 x 136
    k_gemm2<<<g2, 256, G2_SMEM>>>();

    k_gather<<<2048, 256>>>(out);                    // 8
}

// round 8
// speedup vs baseline: 7.0761x; 1.0018x over previous
#include <cuda_runtime.h>
#include <cuda_fp16.h>
#include <math.h>
#include <stdint.h>

#define NTOK 8192
#define NEXP 8
#define IDIM 2816
#define HDIM 1024
#define NROWS (2*NTOK)                 // 16384 routed rows
#define BM 128
#define BK 64                          // halfs of K per smem stage
#define STRH 72                        // smem row stride in halfs (144B)
#define STAGE_B (BM * STRH * 2)        // 18432 bytes per tile stage
#define NSTAGE 3
#define MAX_TILES (NROWS/BM + NEXP)    // 136

// ---- device scratch ----
__device__ __half g_h[(size_t)NROWS * IDIM];            // 92 MB intermediate h (fp16)
__device__ float  g_part[(size_t)NROWS * HDIM];         // 67 MB unweighted GEMM2 partials
__device__ __half g_xh[(size_t)NTOK * HDIM];            // 16 MB X in fp16
__device__ __half g_w1h[(size_t)NEXP * IDIM * HDIM];    // 46 MB
__device__ __half g_w3h[(size_t)NEXP * IDIM * HDIM];    // 46 MB
__device__ __half g_w2h[(size_t)NEXP * HDIM * IDIM];    // 46 MB
__device__ int   g_bin_tok[NROWS];
__device__ int   g_tok_e[NTOK][2];
__device__ float g_tok_w[NTOK][2];
__device__ int   g_pos[NTOK][2];
__device__ int   g_tile_e[MAX_TILES];
__device__ int   g_tile_row0[MAX_TILES];
__device__ int   g_tile_m[MAX_TILES];
__device__ int   g_ntiles;

// ---------------- helpers ----------------
__device__ __forceinline__ void mma_f16(float* c, const uint32_t* a, const uint32_t* b) {
    asm volatile(
        "mma.sync.aligned.m16n8k16.row.col.f32.f16.f16.f32 "
        "{%0,%1,%2,%3},{%4,%5,%6,%7},{%8,%9},{%0,%1,%2,%3};"
        : "+f"(c[0]), "+f"(c[1]), "+f"(c[2]), "+f"(c[3])
        : "r"(a[0]), "r"(a[1]), "r"(a[2]), "r"(a[3]), "r"(b[0]), "r"(b[1]));
}
__device__ __forceinline__ void ldsm4(uint32_t* r, uint32_t addr) {
    asm volatile("ldmatrix.sync.aligned.m8n8.x4.shared.b16 {%0,%1,%2,%3}, [%4];"
        : "=r"(r[0]), "=r"(r[1]), "=r"(r[2]), "=r"(r[3]) : "r"(addr));
}
__device__ __forceinline__ uint32_t smem_u32(const void* p) {
    uint32_t a;
    asm("{ .reg .u64 t; cvta.to.shared.u64 t, %1; cvt.u32.u64 %0, t; }" : "=r"(a) : "l"(p));
    return a;
}
__device__ __forceinline__ void cpa16(uint32_t dst, const void* src) {
    asm volatile("cp.async.cg.shared.global [%0], [%1], 16;" :: "r"(dst), "l"(src));
}
__device__ __forceinline__ void cpa_commit() {
    asm volatile("cp.async.commit_group;" ::: "memory");
}
__device__ __forceinline__ void cpa_wait1() {
    asm volatile("cp.async.wait_group 1;" ::: "memory");
}

// ---------------- small kernels ----------------
// one kernel: fp32->fp16 for X, W1, W3, W2
__global__ void k_cvt_all(const float* __restrict__ X,  const float* __restrict__ W1,
                          const float* __restrict__ W3, const float* __restrict__ W2) {
    const int nX4 = NTOK * HDIM / 4;
    const int nW4 = NEXP * IDIM * HDIM / 4;
    const int total = nX4 + 3 * nW4;
    int stride = gridDim.x * blockDim.x;
    for (int i = blockIdx.x * blockDim.x + threadIdx.x; i < total; i += stride) {
        const float4* src;
        uint2* dst;
        int j;
        if (i < nX4)                { src = (const float4*)X;  dst = (uint2*)g_xh;  j = i; }
        else if (i < nX4 + nW4)     { src = (const float4*)W1; dst = (uint2*)g_w1h; j = i - nX4; }
        else if (i < nX4 + 2*nW4)   { src = (const float4*)W3; dst = (uint2*)g_w3h; j = i - nX4 - nW4; }
        else                        { src = (const float4*)W2; dst = (uint2*)g_w2h; j = i - nX4 - 2*nW4; }
        float4 v = src[j];
        __half2 lo = __floats2half2_rn(v.x, v.y);
        __half2 hi = __floats2half2_rn(v.z, v.w);
        uint2 u; u.x = *(uint32_t*)&lo; u.y = *(uint32_t*)&hi;
        dst[j] = u;
    }
}

__global__ void k_router(const float* __restrict__ logits) {
    int t = blockIdx.x * blockDim.x + threadIdx.x;
    if (t >= NTOK) return;
    float best = -INFINITY, second = -INFINITY;
    int b0 = 0, b1 = 0;
#pragma unroll
    for (int e = 0; e < NEXP; e++) {
        float v = logits[t * NEXP + e];
        if (v > best)        { second = best; b1 = b0; best = v; b0 = e; }
        else if (v > second) { second = v; b1 = e; }
    }
    float w0 = 1.0f / (1.0f + expf(second - best));
    g_tok_e[t][0] = b0;  g_tok_e[t][1] = b1;
    g_tok_w[t][0] = w0;  g_tok_w[t][1] = 1.0f - w0;
}

// single block: histogram + prefix + tile map + scatter
__global__ void k_prep_scatter() {
    __shared__ int hc[NEXP];
    __shared__ int cur[NEXP];
    int tid = threadIdx.x;
    if (tid < NEXP) hc[tid] = 0;
    __syncthreads();
    for (int t = tid; t < NTOK; t += 256) {
        atomicAdd(&hc[g_tok_e[t][0]], 1);
        atomicAdd(&hc[g_tok_e[t][1]], 1);
    }
    __syncthreads();
    if (tid == 0) {
        int off = 0, nt = 0;
        for (int e = 0; e < NEXP; e++) {
            int c = hc[e];
            cur[e] = off;
            for (int r = 0; r < c; r += BM) {
                g_tile_e[nt]    = e;
                g_tile_row0[nt] = off + r;
                g_tile_m[nt]    = min(BM, c - r);
                nt++;
            }
            off += c;
        }
        g_ntiles = nt;
    }
    __syncthreads();
    for (int t = tid; t < NTOK; t += 256) {
#pragma unroll
        for (int k = 0; k < 2; k++) {
            int e = g_tok_e[t][k];
            int p = atomicAdd(&cur[e], 1);
            g_bin_tok[p] = t;
            g_pos[t][k]  = p;
        }
    }
}

// out[t] = w0 * part[p0] + w1 * part[p1]
__global__ void k_gather(float* __restrict__ out) {
    const int n4 = NTOK * HDIM / 4;
    int stride = gridDim.x * blockDim.x;
    for (int i = blockIdx.x * blockDim.x + threadIdx.x; i < n4; i += stride) {
        int t = i >> 8;              // HDIM/4 = 256
        int c = i & 255;
        int p0 = g_pos[t][0], p1 = g_pos[t][1];
        float w0 = g_tok_w[t][0], w1 = g_tok_w[t][1];
        float4 a = ((const float4*)g_part)[(size_t)p0 * 256 + c];
        float4 b = ((const float4*)g_part)[(size_t)p1 * 256 + c];
        float4 o;
        o.x = w0 * a.x + w1 * b.x;
        o.y = w0 * a.y + w1 * b.y;
        o.z = w0 * a.z + w1 * b.z;
        o.w = w0 * a.w + w1 * b.w;
        ((float4*)out)[i] = o;
    }
}

// =====================================================================
// GEMM1 (FP16 mma.sync + ldmatrix + cp.async 3-stage BK=64):
//   h = silu(X@W1^T) * (X@W3^T)
// block 128(M) x 128(N), 8 warps 2(M)x4(N), warp tile 64x32.
// =====================================================================
#define G1_OFF_A   1024
#define G1_OFF_B1  (G1_OFF_A  + NSTAGE*STAGE_B)
#define G1_OFF_B3  (G1_OFF_B1 + NSTAGE*STAGE_B)
#define G1_SMEM    (G1_OFF_B3 + NSTAGE*STAGE_B)   // 166912

__global__ void __launch_bounds__(256, 1)
k_gemm1() {
    if ((int)blockIdx.y >= g_ntiles) return;
    int te   = g_tile_e[blockIdx.y];
    int row0 = g_tile_row0[blockIdx.y];
    int mcnt = g_tile_m[blockIdx.y];
    int nb   = blockIdx.x * 128;

    extern __shared__ __align__(16) char smem[];
    int* s_tok = (int*)smem;
    uint32_t sbase = smem_u32(smem);

    int tid = threadIdx.x;
    if (tid < BM) s_tok[tid] = (tid < mcnt) ? g_bin_tok[row0 + tid] : 0;
    __syncthreads();

    const __half* W1e = g_w1h + (size_t)te * IDIM * HDIM;
    const __half* W3e = g_w3h + (size_t)te * IDIM * HDIM;

    // loader: c = 16B chunk within 64-half row (0..7), r = row base (0..31); rows r+32j
    int c = tid & 7, r = tid >> 3;
    const __half* ag[4];
    const __half* b1g[4];
    const __half* b3g[4];
#pragma unroll
    for (int j = 0; j < 4; j++) {
        ag[j]  = g_xh + (size_t)s_tok[r + 32 * j] * HDIM + c * 8;
        b1g[j] = W1e + (size_t)(nb + r + 32 * j) * HDIM + c * 8;
        b3g[j] = W3e + (size_t)(nb + r + 32 * j) * HDIM + c * 8;
    }
    uint32_t so = (uint32_t)(r * 144 + c * 16);
    const uint32_t ROWSTEP = 32 * 144;

    // warp/lane mapping
    int warpId = tid >> 5, lane = tid & 31;
    int wm = (warpId & 1) * 64;
    int wn = (warpId >> 1) * 32;
    int fr = lane >> 2, fc = lane & 3;

    uint32_t a_lo = (uint32_t)((wm + (lane & 15)) * 144 + (lane >> 4) * 16);
    uint32_t b_lo = (uint32_t)((wn + (lane & 7) + ((lane >> 4) & 1) * 8) * 144 + ((lane >> 3) & 1) * 16);

    float acc1[4][4][4], acc3[4][4][4];
#pragma unroll
    for (int i = 0; i < 4; i++)
#pragma unroll
        for (int j = 0; j < 4; j++)
#pragma unroll
            for (int k = 0; k < 4; k++) { acc1[i][j][k] = 0.f; acc3[i][j][k] = 0.f; }

    const int NIT = HDIM / BK;   // 16

    // prologue: stages 0,1
#pragma unroll
    for (int s = 0; s < NSTAGE - 1; s++) {
        int kt = s * BK;
        uint32_t sa = sbase + G1_OFF_A  + s * STAGE_B + so;
        uint32_t s1 = sbase + G1_OFF_B1 + s * STAGE_B + so;
        uint32_t s3 = sbase + G1_OFF_B3 + s * STAGE_B + so;
#pragma unroll
        for (int j = 0; j < 4; j++) {
            cpa16(sa + j * ROWSTEP, ag[j]  + kt);
            cpa16(s1 + j * ROWSTEP, b1g[j] + kt);
            cpa16(s3 + j * ROWSTEP, b3g[j] + kt);
        }
        cpa_commit();
    }

    for (int it = 0; it < NIT; it++) {
        cpa_wait1();
        __syncthreads();
        // issue stage it+2 (overwrites stage computed at it-1; safe after the sync)
        if (it + NSTAGE - 1 < NIT) {
            int s = (it + NSTAGE - 1) % NSTAGE;
            int kt = (it + NSTAGE - 1) * BK;
            uint32_t sa = sbase + G1_OFF_A  + s * STAGE_B + so;
            uint32_t s1 = sbase + G1_OFF_B1 + s * STAGE_B + so;
            uint32_t s3 = sbase + G1_OFF_B3 + s * STAGE_B + so;
#pragma unroll
            for (int j = 0; j < 4; j++) {
                cpa16(sa + j * ROWSTEP, ag[j]  + kt);
                cpa16(s1 + j * ROWSTEP, b1g[j] + kt);
                cpa16(s3 + j * ROWSTEP, b3g[j] + kt);
            }
        }
        cpa_commit();

        int st = it % NSTAGE;
        uint32_t abase = sbase + G1_OFF_A  + st * STAGE_B + a_lo;
        uint32_t b1b   = sbase + G1_OFF_B1 + st * STAGE_B + b_lo;
        uint32_t b3b   = sbase + G1_OFF_B3 + st * STAGE_B + b_lo;
#pragma unroll
        for (int kk = 0; kk < BK; kk += 16) {
            uint32_t a[4][4];
#pragma unroll
            for (int mt = 0; mt < 4; mt++)
                ldsm4(a[mt], abase + mt * 16 * 144 + kk * 2);
            uint32_t bf1[2][4], bf3[2][4];
#pragma unroll
            for (int p = 0; p < 2; p++) {
                ldsm4(bf1[p], b1b + p * 16 * 144 + kk * 2);
                ldsm4(bf3[p], b3b + p * 16 * 144 + kk * 2);
            }
#pragma unroll
            for (int p = 0; p < 2; p++)
#pragma unroll
                for (int mt = 0; mt < 4; mt++) {
                    mma_f16(acc1[mt][2*p],   a[mt], &bf1[p][0]);
                    mma_f16(acc1[mt][2*p+1], a[mt], &bf1[p][2]);
                    mma_f16(acc3[mt][2*p],   a[mt], &bf3[p][0]);
                    mma_f16(acc3[mt][2*p+1], a[mt], &bf3[p][2]);
                }
        }
    }

    // epilogue: h = silu(c1)*c3 -> g_h (fp16)
#pragma unroll
    for (int mt = 0; mt < 4; mt++) {
        int m_lo = wm + mt * 16 + fr;
        int m_hi = m_lo + 8;
#pragma unroll
        for (int nt = 0; nt < 4; nt++) {
            int col = nb + wn + nt * 8 + fc * 2;
            if (m_lo < mcnt) {
                float c0 = acc1[mt][nt][0], c1 = acc1[mt][nt][1];
                float h0 = c0 / (1.0f + expf(-c0)) * acc3[mt][nt][0];
                float h1 = c1 / (1.0f + expf(-c1)) * acc3[mt][nt][1];
                *(__half2*)&g_h[(size_t)(row0 + m_lo) * IDIM + col] = __floats2half2_rn(h0, h1);
            }
            if (m_hi < mcnt) {
                float c2 = acc1[mt][nt][2], c3 = acc1[mt][nt][3];
                float h2 = c2 / (1.0f + expf(-c2)) * acc3[mt][nt][2];
                float h3 = c3 / (1.0f + expf(-c3)) * acc3[mt][nt][3];
                *(__half2*)&g_h[(size_t)(row0 + m_hi) * IDIM + col] = __floats2half2_rn(h2, h3);
            }
        }
    }
}

// =====================================================================
// GEMM2 (FP16 mma.sync + ldmatrix + cp.async 3-stage BK=64): part = h @ W2^T
// =====================================================================
#define G2_OFF_A  1024
#define G2_OFF_B  (G2_OFF_A + NSTAGE*STAGE_B)
#define G2_SMEM   (G2_OFF_B + NSTAGE*STAGE_B)   // 111616

__global__ void __launch_bounds__(256, 1)
k_gemm2() {
    if ((int)blockIdx.y >= g_ntiles) return;
    int te   = g_tile_e[blockIdx.y];
    int row0 = g_tile_row0[blockIdx.y];
    int mcnt = g_tile_m[blockIdx.y];
    int nb   = blockIdx.x * 128;

    extern __shared__ __align__(16) char smem[];
    uint32_t sbase = smem_u32(smem);
    int tid = threadIdx.x;

    const __half* W2e = g_w2h + (size_t)te * HDIM * IDIM;

    int c = tid & 7, r = tid >> 3;
    const __half* ag[4];
    const __half* bg[4];
#pragma unroll
    for (int j = 0; j < 4; j++) {
        int rr = r + 32 * j;
        ag[j] = g_h + (size_t)(row0 + (rr < mcnt ? rr : 0)) * IDIM + c * 8;
        bg[j] = W2e + (size_t)(nb + rr) * IDIM + c * 8;
    }
    uint32_t so = (uint32_t)(r * 144 + c * 16);
    const uint32_t ROWSTEP = 32 * 144;

    int warpId = tid >> 5, lane = tid & 31;
    int wm = (warpId & 1) * 64;
    int wn = (warpId >> 1) * 32;
    int fr = lane >> 2, fc = lane & 3;

    uint32_t a_lo = (uint32_t)((wm + (lane & 15)) * 144 + (lane >> 4) * 16);
    uint32_t b_lo = (uint32_t)((wn + (lane & 7) + ((lane >> 4) & 1) * 8) * 144 + ((lane >> 3) & 1) * 16);

    float acc[4][4][4];
#pragma unroll
    for (int i = 0; i < 4; i++)
#pragma unroll
        for (int j = 0; j < 4; j++)
#pragma unroll
            for (int k = 0; k < 4; k++) acc[i][j][k] = 0.f;

    const int NIT = IDIM / BK;   // 44

#pragma unroll
    for (int s = 0; s < NSTAGE - 1; s++) {
        int kt = s * BK;
        uint32_t sa = sbase + G2_OFF_A + s * STAGE_B + so;
        uint32_t sb = sbase + G2_OFF_B + s * STAGE_B + so;
#pragma unroll
        for (int j = 0; j < 4; j++) {
            cpa16(sa + j * ROWSTEP, ag[j] + kt);
            cpa16(sb + j * ROWSTEP, bg[j] + kt);
        }
        cpa_commit();
    }

    for (int it = 0; it < NIT; it++) {
        cpa_wait1();
        __syncthreads();
        if (it + NSTAGE - 1 < NIT) {
            int s = (it + NSTAGE - 1) % NSTAGE;
            int kt = (it + NSTAGE - 1) * BK;
            uint32_t sa = sbase + G2_OFF_A + s * STAGE_B + so;
            uint32_t sb = sbase + G2_OFF_B + s * STAGE_B + so;
#pragma unroll
            for (int j = 0; j < 4; j++) {
                cpa16(sa + j * ROWSTEP, ag[j] + kt);
                cpa16(sb + j * ROWSTEP, bg[j] + kt);
            }
        }
        cpa_commit();

        int st = it % NSTAGE;
        uint32_t abase = sbase + G2_OFF_A + st * STAGE_B + a_lo;
        uint32_t bbase = sbase + G2_OFF_B + st * STAGE_B + b_lo;
#pragma unroll
        for (int kk = 0; kk < BK; kk += 16) {
            uint32_t a[4][4];
#pragma unroll
            for (int mt = 0; mt < 4; mt++)
                ldsm4(a[mt], abase + mt * 16 * 144 + kk * 2);
            uint32_t bf[2][4];
#pragma unroll
            for (int p = 0; p < 2; p++)
                ldsm4(bf[p], bbase + p * 16 * 144 + kk * 2);
#pragma unroll
            for (int p = 0; p < 2; p++)
#pragma unroll
                for (int mt = 0; mt < 4; mt++) {
                    mma_f16(acc[mt][2*p],   a[mt], &bf[p][0]);
                    mma_f16(acc[mt][2*p+1], a[mt], &bf[p][2]);
                }
        }
    }

    // epilogue: plain stores of unweighted partials to contiguous bin rows
#pragma unroll
    for (int mt = 0; mt < 4; mt++) {
        int m_lo = wm + mt * 16 + fr;
        int m_hi = m_lo + 8;
#pragma unroll
        for (int nt = 0; nt < 4; nt++) {
            int col = nb + wn + nt * 8 + fc * 2;
            if (m_lo < mcnt) {
                float2 v = make_float2(acc[mt][nt][0], acc[mt][nt][1]);
                *(float2*)&g_part[(size_t)(row0 + m_lo) * HDIM + col] = v;
            }
            if (m_hi < mcnt) {
                float2 v = make_float2(acc[mt][nt][2], acc[mt][nt][3]);
                *(float2*)&g_part[(size_t)(row0 + m_hi) * HDIM + col] = v;
            }
        }
    }
}

// ---------------- launch ----------------
extern "C" void kernel_launch(void* const* d_in, const int* in_sizes, int n_in,
                              void* d_out, int out_size) {
    const float* X  = (const float*)d_in[0];  // [T,H]
    const float* RL = (const float*)d_in[1];  // [T,E]
    const float* W1 = (const float*)d_in[2];  // [E,I,H]
    const float* W3 = (const float*)d_in[3];  // [E,I,H]
    const float* W2 = (const float*)d_in[4];  // [E,H,I]
    float* out = (float*)d_out;               // [T,H]

    cudaFuncSetAttribute(k_gemm1, cudaFuncAttributeMaxDynamicSharedMemorySize, G1_SMEM);
    cudaFuncSetAttribute(k_gemm2, cudaFuncAttributeMaxDynamicSharedMemorySize, G2_SMEM);

    k_cvt_all<<<2048, 256>>>(X, W1, W3, W2);         // 1
    k_router<<<NTOK / 256, 256>>>(RL);               // 2
    k_prep_scatter<<<1, 256>>>();                    // 3

    dim3 g1(IDIM / 128, MAX_TILES);                  // 4: 22 x 136  <- ncu capture slot
    k_gemm1<<<g1, 256, G1_SMEM>>>();

    dim3 g2(HDIM / 128, MAX_TILES);                  // 5: 8 x 136
    k_gemm2<<<g2, 256, G2_SMEM>>>();

    k_gather<<<2048, 256>>>(out);                    // 6
}

// round 9
// speedup vs baseline: 7.1808x; 1.0148x over previous
#include <cuda_runtime.h>
#include <cuda_fp16.h>
#include <math.h>
#include <stdint.h>

#define NTOK 8192
#define NEXP 8
#define IDIM 2816
#define HDIM 1024
#define NROWS (2*NTOK)                 // 16384 routed rows
#define BM 128                         // block M
#define BN 64                          // block N
#define BK 32                          // halfs of K per smem stage
#define STRH 40                        // smem row stride in halfs (80B)
#define STA (BM * STRH * 2)            // 10240 B per A stage
#define STB (BN * STRH * 2)            // 5120 B per B stage
#define NSTAGE 4
#define MAX_TILES (NROWS/BM + NEXP)    // 136

// ---- device scratch ----
__device__ __half g_h[(size_t)NROWS * IDIM];            // 92 MB intermediate h (fp16)
__device__ float  g_part[(size_t)NROWS * HDIM];         // 67 MB unweighted GEMM2 partials
__device__ __half g_xh[(size_t)NTOK * HDIM];            // 16 MB X in fp16
__device__ __half g_w1h[(size_t)NEXP * IDIM * HDIM];    // 46 MB
__device__ __half g_w3h[(size_t)NEXP * IDIM * HDIM];    // 46 MB
__device__ __half g_w2h[(size_t)NEXP * HDIM * IDIM];    // 46 MB
__device__ int   g_bin_tok[NROWS];
__device__ int   g_tok_e[NTOK][2];
__device__ float g_tok_w[NTOK][2];
__device__ int   g_pos[NTOK][2];
__device__ int   g_tile_e[MAX_TILES];
__device__ int   g_tile_row0[MAX_TILES];
__device__ int   g_tile_m[MAX_TILES];
__device__ int   g_ntiles;

// ---------------- helpers ----------------
__device__ __forceinline__ void mma_f16(float* c, const uint32_t* a, const uint32_t* b) {
    asm volatile(
        "mma.sync.aligned.m16n8k16.row.col.f32.f16.f16.f32 "
        "{%0,%1,%2,%3},{%4,%5,%6,%7},{%8,%9},{%0,%1,%2,%3};"
        : "+f"(c[0]), "+f"(c[1]), "+f"(c[2]), "+f"(c[3])
        : "r"(a[0]), "r"(a[1]), "r"(a[2]), "r"(a[3]), "r"(b[0]), "r"(b[1]));
}
__device__ __forceinline__ void ldsm4(uint32_t* r, uint32_t addr) {
    asm volatile("ldmatrix.sync.aligned.m8n8.x4.shared.b16 {%0,%1,%2,%3}, [%4];"
        : "=r"(r[0]), "=r"(r[1]), "=r"(r[2]), "=r"(r[3]) : "r"(addr));
}
__device__ __forceinline__ uint32_t smem_u32(const void* p) {
    uint32_t a;
    asm("{ .reg .u64 t; cvta.to.shared.u64 t, %1; cvt.u32.u64 %0, t; }" : "=r"(a) : "l"(p));
    return a;
}
__device__ __forceinline__ void cpa16(uint32_t dst, const void* src) {
    asm volatile("cp.async.cg.shared.global [%0], [%1], 16;" :: "r"(dst), "l"(src));
}
__device__ __forceinline__ void cpa_commit() {
    asm volatile("cp.async.commit_group;" ::: "memory");
}
__device__ __forceinline__ void cpa_wait2() {
    asm volatile("cp.async.wait_group 2;" ::: "memory");
}

// ---------------- small kernels ----------------
__global__ void k_cvt_all(const float* __restrict__ X,  const float* __restrict__ W1,
                          const float* __restrict__ W3, const float* __restrict__ W2) {
    const int nX4 = NTOK * HDIM / 4;
    const int nW4 = NEXP * IDIM * HDIM / 4;
    const int total = nX4 + 3 * nW4;
    int stride = gridDim.x * blockDim.x;
    for (int i = blockIdx.x * blockDim.x + threadIdx.x; i < total; i += stride) {
        const float4* src;
        uint2* dst;
        int j;
        if (i < nX4)                { src = (const float4*)X;  dst = (uint2*)g_xh;  j = i; }
        else if (i < nX4 + nW4)     { src = (const float4*)W1; dst = (uint2*)g_w1h; j = i - nX4; }
        else if (i < nX4 + 2*nW4)   { src = (const float4*)W3; dst = (uint2*)g_w3h; j = i - nX4 - nW4; }
        else                        { src = (const float4*)W2; dst = (uint2*)g_w2h; j = i - nX4 - 2*nW4; }
        float4 v = src[j];
        __half2 lo = __floats2half2_rn(v.x, v.y);
        __half2 hi = __floats2half2_rn(v.z, v.w);
        uint2 u; u.x = *(uint32_t*)&lo; u.y = *(uint32_t*)&hi;
        dst[j] = u;
    }
}

__global__ void k_router(const float* __restrict__ logits) {
    int t = blockIdx.x * blockDim.x + threadIdx.x;
    if (t >= NTOK) return;
    float best = -INFINITY, second = -INFINITY;
    int b0 = 0, b1 = 0;
#pragma unroll
    for (int e = 0; e < NEXP; e++) {
        float v = logits[t * NEXP + e];
        if (v > best)        { second = best; b1 = b0; best = v; b0 = e; }
        else if (v > second) { second = v; b1 = e; }
    }
    float w0 = 1.0f / (1.0f + expf(second - best));
    g_tok_e[t][0] = b0;  g_tok_e[t][1] = b1;
    g_tok_w[t][0] = w0;  g_tok_w[t][1] = 1.0f - w0;
}

__global__ void k_prep_scatter() {
    __shared__ int hc[NEXP];
    __shared__ int cur[NEXP];
    int tid = threadIdx.x;
    if (tid < NEXP) hc[tid] = 0;
    __syncthreads();
    for (int t = tid; t < NTOK; t += 256) {
        atomicAdd(&hc[g_tok_e[t][0]], 1);
        atomicAdd(&hc[g_tok_e[t][1]], 1);
    }
    __syncthreads();
    if (tid == 0) {
        int off = 0, nt = 0;
        for (int e = 0; e < NEXP; e++) {
            int c = hc[e];
            cur[e] = off;
            for (int r = 0; r < c; r += BM) {
                g_tile_e[nt]    = e;
                g_tile_row0[nt] = off + r;
                g_tile_m[nt]    = min(BM, c - r);
                nt++;
            }
            off += c;
        }
        g_ntiles = nt;
    }
    __syncthreads();
    for (int t = tid; t < NTOK; t += 256) {
#pragma unroll
        for (int k = 0; k < 2; k++) {
            int e = g_tok_e[t][k];
            int p = atomicAdd(&cur[e], 1);
            g_bin_tok[p] = t;
            g_pos[t][k]  = p;
        }
    }
}

__global__ void k_gather(float* __restrict__ out) {
    const int n4 = NTOK * HDIM / 4;
    int stride = gridDim.x * blockDim.x;
    for (int i = blockIdx.x * blockDim.x + threadIdx.x; i < n4; i += stride) {
        int t = i >> 8;
        int c = i & 255;
        int p0 = g_pos[t][0], p1 = g_pos[t][1];
        float w0 = g_tok_w[t][0], w1 = g_tok_w[t][1];
        float4 a = ((const float4*)g_part)[(size_t)p0 * 256 + c];
        float4 b = ((const float4*)g_part)[(size_t)p1 * 256 + c];
        float4 o;
        o.x = w0 * a.x + w1 * b.x;
        o.y = w0 * a.y + w1 * b.y;
        o.z = w0 * a.z + w1 * b.z;
        o.w = w0 * a.w + w1 * b.w;
        ((float4*)out)[i] = o;
    }
}

// =====================================================================
// GEMM1: h = silu(X@W1^T) * (X@W3^T)
// 128 threads (4 warps, 2Mx2N of 64x32 warp tiles), block tile 128x64,
// BK=32 halfs, 4-stage cp.async, 2 CTAs/SM.
// smem: s_tok[1024] | A[4][10240] | B1[4][5120] | B3[4][5120] = 82944 B
// =====================================================================
#define G1_OFF_A   1024
#define G1_OFF_B1  (G1_OFF_A  + NSTAGE*STA)    // 41984
#define G1_OFF_B3  (G1_OFF_B1 + NSTAGE*STB)    // 62464
#define G1_SMEM    (G1_OFF_B3 + NSTAGE*STB)    // 82944

__global__ void __launch_bounds__(128, 2)
k_gemm1() {
    if ((int)blockIdx.y >= g_ntiles) return;
    int te   = g_tile_e[blockIdx.y];
    int row0 = g_tile_row0[blockIdx.y];
    int mcnt = g_tile_m[blockIdx.y];
    int nb   = blockIdx.x * BN;

    extern __shared__ __align__(16) char smem[];
    int* s_tok = (int*)smem;
    uint32_t sbase = smem_u32(smem);

    int tid = threadIdx.x;
    if (tid < BM) s_tok[tid] = (tid < mcnt) ? g_bin_tok[row0 + tid] : 0;
    __syncthreads();

    const __half* W1e = g_w1h + (size_t)te * IDIM * HDIM;
    const __half* W3e = g_w3h + (size_t)te * IDIM * HDIM;

    // loader: c = 16B chunk (0..3), r = row base (0..31)
    int c = tid & 3, r = tid >> 2;
    const __half* ag[4];
    const __half* b1g[2];
    const __half* b3g[2];
#pragma unroll
    for (int j = 0; j < 4; j++)
        ag[j] = g_xh + (size_t)s_tok[r + 32 * j] * HDIM + c * 8;
#pragma unroll
    for (int j = 0; j < 2; j++) {
        b1g[j] = W1e + (size_t)(nb + r + 32 * j) * HDIM + c * 8;
        b3g[j] = W3e + (size_t)(nb + r + 32 * j) * HDIM + c * 8;
    }
    uint32_t so = (uint32_t)(r * 80 + c * 16);
    const uint32_t RS = 32 * 80;   // +32 rows in smem

    // warp/lane mapping: 4 warps, 2(M) x 2(N)
    int warpId = tid >> 5, lane = tid & 31;
    int wm = (warpId & 1) * 64;
    int wn = (warpId >> 1) * 32;
    int fr = lane >> 2, fc = lane & 3;

    uint32_t a_lo = (uint32_t)((wm + (lane & 15)) * 80 + (lane >> 4) * 16);
    uint32_t b_lo = (uint32_t)((wn + (lane & 7) + ((lane >> 4) & 1) * 8) * 80 + ((lane >> 3) & 1) * 16);

    float acc1[4][4][4], acc3[4][4][4];
#pragma unroll
    for (int i = 0; i < 4; i++)
#pragma unroll
        for (int j = 0; j < 4; j++)
#pragma unroll
            for (int k = 0; k < 4; k++) { acc1[i][j][k] = 0.f; acc3[i][j][k] = 0.f; }

    const int NIT = HDIM / BK;   // 32

    // prologue: stages 0..2
#pragma unroll
    for (int s = 0; s < NSTAGE - 1; s++) {
        int kt = s * BK;
        uint32_t sa = sbase + G1_OFF_A  + s * STA + so;
        uint32_t s1 = sbase + G1_OFF_B1 + s * STB + so;
        uint32_t s3 = sbase + G1_OFF_B3 + s * STB + so;
#pragma unroll
        for (int j = 0; j < 4; j++) cpa16(sa + j * RS, ag[j] + kt);
#pragma unroll
        for (int j = 0; j < 2; j++) {
            cpa16(s1 + j * RS, b1g[j] + kt);
            cpa16(s3 + j * RS, b3g[j] + kt);
        }
        cpa_commit();
    }

    for (int it = 0; it < NIT; it++) {
        cpa_wait2();
        __syncthreads();
        if (it + NSTAGE - 1 < NIT) {
            int s = (it + NSTAGE - 1) & (NSTAGE - 1);
            int kt = (it + NSTAGE - 1) * BK;
            uint32_t sa = sbase + G1_OFF_A  + s * STA + so;
            uint32_t s1 = sbase + G1_OFF_B1 + s * STB + so;
            uint32_t s3 = sbase + G1_OFF_B3 + s * STB + so;
#pragma unroll
            for (int j = 0; j < 4; j++) cpa16(sa + j * RS, ag[j] + kt);
#pragma unroll
            for (int j = 0; j < 2; j++) {
                cpa16(s1 + j * RS, b1g[j] + kt);
                cpa16(s3 + j * RS, b3g[j] + kt);
            }
        }
        cpa_commit();

        int st = it & (NSTAGE - 1);
        uint32_t abase = sbase + G1_OFF_A  + st * STA + a_lo;
        uint32_t b1b   = sbase + G1_OFF_B1 + st * STB + b_lo;
        uint32_t b3b   = sbase + G1_OFF_B3 + st * STB + b_lo;
#pragma unroll
        for (int kk = 0; kk < BK; kk += 16) {
            uint32_t a[4][4];
#pragma unroll
            for (int mt = 0; mt < 4; mt++)
                ldsm4(a[mt], abase + mt * 16 * 80 + kk * 2);
            uint32_t bf1[2][4], bf3[2][4];
#pragma unroll
            for (int p = 0; p < 2; p++) {
                ldsm4(bf1[p], b1b + p * 16 * 80 + kk * 2);
                ldsm4(bf3[p], b3b + p * 16 * 80 + kk * 2);
            }
#pragma unroll
            for (int p = 0; p < 2; p++)
#pragma unroll
                for (int mt = 0; mt < 4; mt++) {
                    mma_f16(acc1[mt][2*p],   a[mt], &bf1[p][0]);
                    mma_f16(acc1[mt][2*p+1], a[mt], &bf1[p][2]);
                    mma_f16(acc3[mt][2*p],   a[mt], &bf3[p][0]);
                    mma_f16(acc3[mt][2*p+1], a[mt], &bf3[p][2]);
                }
        }
    }

    // epilogue: h = silu(c1)*c3 -> g_h (fp16)
#pragma unroll
    for (int mt = 0; mt < 4; mt++) {
        int m_lo = wm + mt * 16 + fr;
        int m_hi = m_lo + 8;
#pragma unroll
        for (int nt = 0; nt < 4; nt++) {
            int col = nb + wn + nt * 8 + fc * 2;
            if (m_lo < mcnt) {
                float c0 = acc1[mt][nt][0], c1 = acc1[mt][nt][1];
                float h0 = c0 / (1.0f + expf(-c0)) * acc3[mt][nt][0];
                float h1 = c1 / (1.0f + expf(-c1)) * acc3[mt][nt][1];
                *(__half2*)&g_h[(size_t)(row0 + m_lo) * IDIM + col] = __floats2half2_rn(h0, h1);
            }
            if (m_hi < mcnt) {
                float c2 = acc1[mt][nt][2], c3 = acc1[mt][nt][3];
                float h2 = c2 / (1.0f + expf(-c2)) * acc3[mt][nt][2];
                float h3 = c3 / (1.0f + expf(-c3)) * acc3[mt][nt][3];
                *(__half2*)&g_h[(size_t)(row0 + m_hi) * IDIM + col] = __floats2half2_rn(h2, h3);
            }
        }
    }
}

// =====================================================================
// GEMM2: part = h @ W2^T
// 128 threads, block tile 128x64, BK=32, 4-stage, 2 CTAs/SM.
// smem: 1024 | A[4][10240] | B[4][5120] = 62464 B
// =====================================================================
#define G2_OFF_A  1024
#define G2_OFF_B  (G2_OFF_A + NSTAGE*STA)    // 41984
#define G2_SMEM   (G2_OFF_B + NSTAGE*STB)    // 62464

__global__ void __launch_bounds__(128, 2)
k_gemm2() {
    if ((int)blockIdx.y >= g_ntiles) return;
    int te   = g_tile_e[blockIdx.y];
    int row0 = g_tile_row0[blockIdx.y];
    int mcnt = g_tile_m[blockIdx.y];
    int nb   = blockIdx.x * BN;

    extern __shared__ __align__(16) char smem[];
    uint32_t sbase = smem_u32(smem);
    int tid = threadIdx.x;

    const __half* W2e = g_w2h + (size_t)te * HDIM * IDIM;

    int c = tid & 3, r = tid >> 2;
    const __half* ag[4];
    const __half* bg[2];
#pragma unroll
    for (int j = 0; j < 4; j++) {
        int rr = r + 32 * j;
        ag[j] = g_h + (size_t)(row0 + (rr < mcnt ? rr : 0)) * IDIM + c * 8;
    }
#pragma unroll
    for (int j = 0; j < 2; j++)
        bg[j] = W2e + (size_t)(nb + r + 32 * j) * IDIM + c * 8;
    uint32_t so = (uint32_t)(r * 80 + c * 16);
    const uint32_t RS = 32 * 80;

    int warpId = tid >> 5, lane = tid & 31;
    int wm = (warpId & 1) * 64;
    int wn = (warpId >> 1) * 32;
    int fr = lane >> 2, fc = lane & 3;

    uint32_t a_lo = (uint32_t)((wm + (lane & 15)) * 80 + (lane >> 4) * 16);
    uint32_t b_lo = (uint32_t)((wn + (lane & 7) + ((lane >> 4) & 1) * 8) * 80 + ((lane >> 3) & 1) * 16);

    float acc[4][4][4];
#pragma unroll
    for (int i = 0; i < 4; i++)
#pragma unroll
        for (int j = 0; j < 4; j++)
#pragma unroll
            for (int k = 0; k < 4; k++) acc[i][j][k] = 0.f;

    const int NIT = IDIM / BK;   // 88

#pragma unroll
    for (int s = 0; s < NSTAGE - 1; s++) {
        int kt = s * BK;
        uint32_t sa = sbase + G2_OFF_A + s * STA + so;
        uint32_t sb = sbase + G2_OFF_B + s * STB + so;
#pragma unroll
        for (int j = 0; j < 4; j++) cpa16(sa + j * RS, ag[j] + kt);
#pragma unroll
        for (int j = 0; j < 2; j++) cpa16(sb + j * RS, bg[j] + kt);
        cpa_commit();
    }

    for (int it = 0; it < NIT; it++) {
        cpa_wait2();
        __syncthreads();
        if (it + NSTAGE - 1 < NIT) {
            int s = (it + NSTAGE - 1) & (NSTAGE - 1);
            int kt = (it + NSTAGE - 1) * BK;
            uint32_t sa = sbase + G2_OFF_A + s * STA + so;
            uint32_t sb = sbase + G2_OFF_B + s * STB + so;
#pragma unroll
            for (int j = 0; j < 4; j++) cpa16(sa + j * RS, ag[j] + kt);
#pragma unroll
            for (int j = 0; j < 2; j++) cpa16(sb + j * RS, bg[j] + kt);
        }
        cpa_commit();

        int st = it & (NSTAGE - 1);
        uint32_t abase = sbase + G2_OFF_A + st * STA + a_lo;
        uint32_t bbase = sbase + G2_OFF_B + st * STB + b_lo;
#pragma unroll
        for (int kk = 0; kk < BK; kk += 16) {
            uint32_t a[4][4];
#pragma unroll
            for (int mt = 0; mt < 4; mt++)
                ldsm4(a[mt], abase + mt * 16 * 80 + kk * 2);
            uint32_t bf[2][4];
#pragma unroll
            for (int p = 0; p < 2; p++)
                ldsm4(bf[p], bbase + p * 16 * 80 + kk * 2);
#pragma unroll
            for (int p = 0; p < 2; p++)
#pragma unroll
                for (int mt = 0; mt < 4; mt++) {
                    mma_f16(acc[mt][2*p],   a[mt], &bf[p][0]);
                    mma_f16(acc[mt][2*p+1], a[mt], &bf[p][2]);
                }
        }
    }

    // epilogue: plain stores of unweighted partials
#pragma unroll
    for (int mt = 0; mt < 4; mt++) {
        int m_lo = wm + mt * 16 + fr;
        int m_hi = m_lo + 8;
#pragma unroll
        for (int nt = 0; nt < 4; nt++) {
            int col = nb + wn + nt * 8 + fc * 2;
            if (m_lo < mcnt) {
                float2 v = make_float2(acc[mt][nt][0], acc[mt][nt][1]);
                *(float2*)&g_part[(size_t)(row0 + m_lo) * HDIM + col] = v;
            }
            if (m_hi < mcnt) {
                float2 v = make_float2(acc[mt][nt][2], acc[mt][nt][3]);
                *(float2*)&g_part[(size_t)(row0 + m_hi) * HDIM + col] = v;
            }
        }
    }
}

// ---------------- launch ----------------
extern "C" void kernel_launch(void* const* d_in, const int* in_sizes, int n_in,
                              void* d_out, int out_size) {
    const float* X  = (const float*)d_in[0];  // [T,H]
    const float* RL = (const float*)d_in[1];  // [T,E]
    const float* W1 = (const float*)d_in[2];  // [E,I,H]
    const float* W3 = (const float*)d_in[3];  // [E,I,H]
    const float* W2 = (const float*)d_in[4];  // [E,H,I]
    float* out = (float*)d_out;               // [T,H]

    cudaFuncSetAttribute(k_gemm1, cudaFuncAttributeMaxDynamicSharedMemorySize, G1_SMEM);
    cudaFuncSetAttribute(k_gemm2, cudaFuncAttributeMaxDynamicSharedMemorySize, G2_SMEM);

    k_cvt_all<<<2048, 256>>>(X, W1, W3, W2);         // 1
    k_router<<<NTOK / 256, 256>>>(RL);               // 2
    k_prep_scatter<<<1, 256>>>();                    // 3

    dim3 g1(IDIM / BN, MAX_TILES);                   // 4: 44 x 136  <- ncu capture slot
    k_gemm1<<<g1, 128, G1_SMEM>>>();

    dim3 g2(HDIM / BN, MAX_TILES);                   // 5: 16 x 136
    k_gemm2<<<g2, 128, G2_SMEM>>>();

    k_gather<<<2048, 256>>>(out);                    // 6
}

// round 10
// speedup vs baseline: 7.2165x; 1.0050x over previous
#include <cuda_runtime.h>
#include <cuda_fp16.h>
#include <math.h>
#include <stdint.h>

#define NTOK 8192
#define NEXP 8
#define IDIM 2816
#define HDIM 1024
#define NROWS (2*NTOK)                 // 16384 routed rows
#define BM 128                         // block M
#define BN 64                          // block N
#define BK 32                          // halfs of K per smem stage
#define STRH 40                        // smem row stride in halfs (80B)
#define STA (BM * STRH * 2)            // 10240 B per A stage
#define STB (BN * STRH * 2)            // 5120 B per B stage
#define NSTAGE 4
#define MAX_TILES (NROWS/BM + NEXP)    // 136

// ---- device scratch ----
__device__ __half g_h[(size_t)NROWS * IDIM];            // 92 MB intermediate h (fp16)
__device__ float  g_part[(size_t)NROWS * HDIM];         // 67 MB unweighted GEMM2 partials
__device__ __half g_xh[(size_t)NTOK * HDIM];            // 16 MB X in fp16
__device__ __half g_w1h[(size_t)NEXP * IDIM * HDIM];    // 46 MB
__device__ __half g_w3h[(size_t)NEXP * IDIM * HDIM];    // 46 MB
__device__ __half g_w2h[(size_t)NEXP * HDIM * IDIM];    // 46 MB
__device__ int   g_bin_tok[NROWS];
__device__ int   g_tok_e[NTOK][2];
__device__ float g_tok_w[NTOK][2];
__device__ int   g_pos[NTOK][2];
__device__ int   g_tile_e[MAX_TILES];
__device__ int   g_tile_row0[MAX_TILES];
__device__ int   g_tile_m[MAX_TILES];
__device__ int   g_ntiles;

// ---------------- helpers ----------------
__device__ __forceinline__ void mma_f16(float* c, const uint32_t* a, const uint32_t* b) {
    asm volatile(
        "mma.sync.aligned.m16n8k16.row.col.f32.f16.f16.f32 "
        "{%0,%1,%2,%3},{%4,%5,%6,%7},{%8,%9},{%0,%1,%2,%3};"
        : "+f"(c[0]), "+f"(c[1]), "+f"(c[2]), "+f"(c[3])
        : "r"(a[0]), "r"(a[1]), "r"(a[2]), "r"(a[3]), "r"(b[0]), "r"(b[1]));
}
__device__ __forceinline__ void ldsm4(uint32_t* r, uint32_t addr) {
    asm volatile("ldmatrix.sync.aligned.m8n8.x4.shared.b16 {%0,%1,%2,%3}, [%4];"
        : "=r"(r[0]), "=r"(r[1]), "=r"(r[2]), "=r"(r[3]) : "r"(addr));
}
__device__ __forceinline__ uint32_t smem_u32(const void* p) {
    uint32_t a;
    asm("{ .reg .u64 t; cvta.to.shared.u64 t, %1; cvt.u32.u64 %0, t; }" : "=r"(a) : "l"(p));
    return a;
}
__device__ __forceinline__ void cpa16(uint32_t dst, const void* src) {
    asm volatile("cp.async.cg.shared.global [%0], [%1], 16;" :: "r"(dst), "l"(src));
}
__device__ __forceinline__ void cpa_commit() {
    asm volatile("cp.async.commit_group;" ::: "memory");
}
__device__ __forceinline__ void cpa_wait2() {
    asm volatile("cp.async.wait_group 2;" ::: "memory");
}

// ---------------- small kernels ----------------
__global__ void k_cvt_all(const float* __restrict__ X,  const float* __restrict__ W1,
                          const float* __restrict__ W3, const float* __restrict__ W2) {
    const int nX4 = NTOK * HDIM / 4;
    const int nW4 = NEXP * IDIM * HDIM / 4;
    const int total = nX4 + 3 * nW4;
    int stride = gridDim.x * blockDim.x;
    for (int i = blockIdx.x * blockDim.x + threadIdx.x; i < total; i += stride) {
        const float4* src;
        uint2* dst;
        int j;
        if (i < nX4)                { src = (const float4*)X;  dst = (uint2*)g_xh;  j = i; }
        else if (i < nX4 + nW4)     { src = (const float4*)W1; dst = (uint2*)g_w1h; j = i - nX4; }
        else if (i < nX4 + 2*nW4)   { src = (const float4*)W3; dst = (uint2*)g_w3h; j = i - nX4 - nW4; }
        else                        { src = (const float4*)W2; dst = (uint2*)g_w2h; j = i - nX4 - 2*nW4; }
        float4 v = src[j];
        __half2 lo = __floats2half2_rn(v.x, v.y);
        __half2 hi = __floats2half2_rn(v.z, v.w);
        uint2 u; u.x = *(uint32_t*)&lo; u.y = *(uint32_t*)&hi;
        dst[j] = u;
    }
}

__global__ void k_router(const float* __restrict__ logits) {
    int t = blockIdx.x * blockDim.x + threadIdx.x;
    if (t >= NTOK) return;
    float best = -INFINITY, second = -INFINITY;
    int b0 = 0, b1 = 0;
#pragma unroll
    for (int e = 0; e < NEXP; e++) {
        float v = logits[t * NEXP + e];
        if (v > best)        { second = best; b1 = b0; best = v; b0 = e; }
        else if (v > second) { second = v; b1 = e; }
    }
    float w0 = 1.0f / (1.0f + expf(second - best));
    g_tok_e[t][0] = b0;  g_tok_e[t][1] = b1;
    g_tok_w[t][0] = w0;  g_tok_w[t][1] = 1.0f - w0;
}

__global__ void k_prep_scatter() {
    __shared__ int hc[NEXP];
    __shared__ int cur[NEXP];
    int tid = threadIdx.x;
    if (tid < NEXP) hc[tid] = 0;
    __syncthreads();
    for (int t = tid; t < NTOK; t += 256) {
        atomicAdd(&hc[g_tok_e[t][0]], 1);
        atomicAdd(&hc[g_tok_e[t][1]], 1);
    }
    __syncthreads();
    if (tid == 0) {
        int off = 0, nt = 0;
        for (int e = 0; e < NEXP; e++) {
            int c = hc[e];
            cur[e] = off;
            for (int r = 0; r < c; r += BM) {
                g_tile_e[nt]    = e;
                g_tile_row0[nt] = off + r;
                g_tile_m[nt]    = min(BM, c - r);
                nt++;
            }
            off += c;
        }
        g_ntiles = nt;
    }
    __syncthreads();
    for (int t = tid; t < NTOK; t += 256) {
#pragma unroll
        for (int k = 0; k < 2; k++) {
            int e = g_tok_e[t][k];
            int p = atomicAdd(&cur[e], 1);
            g_bin_tok[p] = t;
            g_pos[t][k]  = p;
        }
    }
}

__global__ void k_gather(float* __restrict__ out) {
    const int n4 = NTOK * HDIM / 4;
    int stride = gridDim.x * blockDim.x;
    for (int i = blockIdx.x * blockDim.x + threadIdx.x; i < n4; i += stride) {
        int t = i >> 8;
        int c = i & 255;
        int p0 = g_pos[t][0], p1 = g_pos[t][1];
        float w0 = g_tok_w[t][0], w1 = g_tok_w[t][1];
        float4 a = ((const float4*)g_part)[(size_t)p0 * 256 + c];
        float4 b = ((const float4*)g_part)[(size_t)p1 * 256 + c];
        float4 o;
        o.x = w0 * a.x + w1 * b.x;
        o.y = w0 * a.y + w1 * b.y;
        o.z = w0 * a.z + w1 * b.z;
        o.w = w0 * a.w + w1 * b.w;
        ((float4*)out)[i] = o;
    }
}

// =====================================================================
// GEMM1: h = silu(X@W1^T) * (X@W3^T)
// 256 threads (8 warps, 4Mx2N of 32x32 warp tiles), block tile 128x64,
// BK=32 halfs, 4-stage cp.async, 2 CTAs/SM -> 16 warps/SM.
// smem: s_tok[1024] | A[4][10240] | B1[4][5120] | B3[4][5120] = 82944 B
// =====================================================================
#define G1_OFF_A   1024
#define G1_OFF_B1  (G1_OFF_A  + NSTAGE*STA)    // 41984
#define G1_OFF_B3  (G1_OFF_B1 + NSTAGE*STB)    // 62464
#define G1_SMEM    (G1_OFF_B3 + NSTAGE*STB)    // 82944

__global__ void __launch_bounds__(256, 2)
k_gemm1() {
    if ((int)blockIdx.y >= g_ntiles) return;
    int te   = g_tile_e[blockIdx.y];
    int row0 = g_tile_row0[blockIdx.y];
    int mcnt = g_tile_m[blockIdx.y];
    int nb   = blockIdx.x * BN;

    extern __shared__ __align__(16) char smem[];
    int* s_tok = (int*)smem;
    uint32_t sbase = smem_u32(smem);

    int tid = threadIdx.x;
    if (tid < BM) s_tok[tid] = (tid < mcnt) ? g_bin_tok[row0 + tid] : 0;
    __syncthreads();

    const __half* W1e = g_w1h + (size_t)te * IDIM * HDIM;
    const __half* W3e = g_w3h + (size_t)te * IDIM * HDIM;

    // loader: 256 threads. c = 16B chunk (0..3), r = row (0..63).
    // A rows r, r+64 (2 cpa); B1 row r (1 cpa); B3 row r (1 cpa).
    int c = tid & 3, r = tid >> 2;
    const __half* ag0 = g_xh + (size_t)s_tok[r]      * HDIM + c * 8;
    const __half* ag1 = g_xh + (size_t)s_tok[r + 64] * HDIM + c * 8;
    const __half* b1g = W1e + (size_t)(nb + r) * HDIM + c * 8;
    const __half* b3g = W3e + (size_t)(nb + r) * HDIM + c * 8;
    uint32_t so = (uint32_t)(r * 80 + c * 16);
    const uint32_t RS64 = 64 * 80;   // +64 rows in smem

    // warp/lane mapping: 8 warps, 4(M) x 2(N), warp tile 32x32
    int warpId = tid >> 5, lane = tid & 31;
    int wm = (warpId & 3) * 32;
    int wn = (warpId >> 2) * 32;
    int fr = lane >> 2, fc = lane & 3;

    uint32_t a_lo = (uint32_t)((wm + (lane & 15)) * 80 + (lane >> 4) * 16);
    uint32_t b_lo = (uint32_t)((wn + (lane & 7) + ((lane >> 4) & 1) * 8) * 80 + ((lane >> 3) & 1) * 16);

    float acc1[2][4][4], acc3[2][4][4];
#pragma unroll
    for (int i = 0; i < 2; i++)
#pragma unroll
        for (int j = 0; j < 4; j++)
#pragma unroll
            for (int k = 0; k < 4; k++) { acc1[i][j][k] = 0.f; acc3[i][j][k] = 0.f; }

    const int NIT = HDIM / BK;   // 32

    // prologue: stages 0..2
#pragma unroll
    for (int s = 0; s < NSTAGE - 1; s++) {
        int kt = s * BK;
        uint32_t sa = sbase + G1_OFF_A  + s * STA + so;
        uint32_t s1 = sbase + G1_OFF_B1 + s * STB + so;
        uint32_t s3 = sbase + G1_OFF_B3 + s * STB + so;
        cpa16(sa, ag0 + kt);
        cpa16(sa + RS64, ag1 + kt);
        cpa16(s1, b1g + kt);
        cpa16(s3, b3g + kt);
        cpa_commit();
    }

    for (int it = 0; it < NIT; it++) {
        cpa_wait2();
        __syncthreads();
        if (it + NSTAGE - 1 < NIT) {
            int s = (it + NSTAGE - 1) & (NSTAGE - 1);
            int kt = (it + NSTAGE - 1) * BK;
            uint32_t sa = sbase + G1_OFF_A  + s * STA + so;
            uint32_t s1 = sbase + G1_OFF_B1 + s * STB + so;
            uint32_t s3 = sbase + G1_OFF_B3 + s * STB + so;
            cpa16(sa, ag0 + kt);
            cpa16(sa + RS64, ag1 + kt);
            cpa16(s1, b1g + kt);
            cpa16(s3, b3g + kt);
        }
        cpa_commit();

        int st = it & (NSTAGE - 1);
        uint32_t abase = sbase + G1_OFF_A  + st * STA + a_lo;
        uint32_t b1b   = sbase + G1_OFF_B1 + st * STB + b_lo;
        uint32_t b3b   = sbase + G1_OFF_B3 + st * STB + b_lo;
#pragma unroll
        for (int kk = 0; kk < BK; kk += 16) {
            uint32_t a[2][4];
#pragma unroll
            for (int mt = 0; mt < 2; mt++)
                ldsm4(a[mt], abase + mt * 16 * 80 + kk * 2);
            uint32_t bf1[2][4], bf3[2][4];
#pragma unroll
            for (int p = 0; p < 2; p++) {
                ldsm4(bf1[p], b1b + p * 16 * 80 + kk * 2);
                ldsm4(bf3[p], b3b + p * 16 * 80 + kk * 2);
            }
#pragma unroll
            for (int p = 0; p < 2; p++)
#pragma unroll
                for (int mt = 0; mt < 2; mt++) {
                    mma_f16(acc1[mt][2*p],   a[mt], &bf1[p][0]);
                    mma_f16(acc1[mt][2*p+1], a[mt], &bf1[p][2]);
                    mma_f16(acc3[mt][2*p],   a[mt], &bf3[p][0]);
                    mma_f16(acc3[mt][2*p+1], a[mt], &bf3[p][2]);
                }
        }
    }

    // epilogue: h = silu(c1)*c3 -> g_h (fp16)
#pragma unroll
    for (int mt = 0; mt < 2; mt++) {
        int m_lo = wm + mt * 16 + fr;
        int m_hi = m_lo + 8;
#pragma unroll
        for (int nt = 0; nt < 4; nt++) {
            int col = nb + wn + nt * 8 + fc * 2;
            if (m_lo < mcnt) {
                float c0 = acc1[mt][nt][0], c1 = acc1[mt][nt][1];
                float h0 = c0 / (1.0f + expf(-c0)) * acc3[mt][nt][0];
                float h1 = c1 / (1.0f + expf(-c1)) * acc3[mt][nt][1];
                *(__half2*)&g_h[(size_t)(row0 + m_lo) * IDIM + col] = __floats2half2_rn(h0, h1);
            }
            if (m_hi < mcnt) {
                float c2 = acc1[mt][nt][2], c3 = acc1[mt][nt][3];
                float h2 = c2 / (1.0f + expf(-c2)) * acc3[mt][nt][2];
                float h3 = c3 / (1.0f + expf(-c3)) * acc3[mt][nt][3];
                *(__half2*)&g_h[(size_t)(row0 + m_hi) * IDIM + col] = __floats2half2_rn(h2, h3);
            }
        }
    }
}

// =====================================================================
// GEMM2: part = h @ W2^T
// 256 threads, 32x32 warp tiles (4Mx2N), block 128x64, BK=32, 4-stage,
// 2 CTAs/SM -> 16 warps/SM.
// smem: 1024 | A[4][10240] | B[4][5120] = 62464 B
// =====================================================================
#define G2_OFF_A  1024
#define G2_OFF_B  (G2_OFF_A + NSTAGE*STA)    // 41984
#define G2_SMEM   (G2_OFF_B + NSTAGE*STB)    // 62464

__global__ void __launch_bounds__(256, 2)
k_gemm2() {
    if ((int)blockIdx.y >= g_ntiles) return;
    int te   = g_tile_e[blockIdx.y];
    int row0 = g_tile_row0[blockIdx.y];
    int mcnt = g_tile_m[blockIdx.y];
    int nb   = blockIdx.x * BN;

    extern __shared__ __align__(16) char smem[];
    uint32_t sbase = smem_u32(smem);
    int tid = threadIdx.x;

    const __half* W2e = g_w2h + (size_t)te * HDIM * IDIM;

    int c = tid & 3, r = tid >> 2;
    int r0e = (r      < mcnt) ? r      : 0;
    int r1e = (r + 64 < mcnt) ? r + 64 : 0;
    const __half* ag0 = g_h + (size_t)(row0 + r0e) * IDIM + c * 8;
    const __half* ag1 = g_h + (size_t)(row0 + r1e) * IDIM + c * 8;
    const __half* bg  = W2e + (size_t)(nb + r) * IDIM + c * 8;
    uint32_t so = (uint32_t)(r * 80 + c * 16);
    const uint32_t RS64 = 64 * 80;

    int warpId = tid >> 5, lane = tid & 31;
    int wm = (warpId & 3) * 32;
    int wn = (warpId >> 2) * 32;
    int fr = lane >> 2, fc = lane & 3;

    uint32_t a_lo = (uint32_t)((wm + (lane & 15)) * 80 + (lane >> 4) * 16);
    uint32_t b_lo = (uint32_t)((wn + (lane & 7) + ((lane >> 4) & 1) * 8) * 80 + ((lane >> 3) & 1) * 16);

    float acc[2][4][4];
#pragma unroll
    for (int i = 0; i < 2; i++)
#pragma unroll
        for (int j = 0; j < 4; j++)
#pragma unroll
            for (int k = 0; k < 4; k++) acc[i][j][k] = 0.f;

    const int NIT = IDIM / BK;   // 88

#pragma unroll
    for (int s = 0; s < NSTAGE - 1; s++) {
        int kt = s * BK;
        uint32_t sa = sbase + G2_OFF_A + s * STA + so;
        uint32_t sb = sbase + G2_OFF_B + s * STB + so;
        cpa16(sa, ag0 + kt);
        cpa16(sa + RS64, ag1 + kt);
        cpa16(sb, bg + kt);
        cpa_commit();
    }

    for (int it = 0; it < NIT; it++) {
        cpa_wait2();
        __syncthreads();
        if (it + NSTAGE - 1 < NIT) {
            int s = (it + NSTAGE - 1) & (NSTAGE - 1);
            int kt = (it + NSTAGE - 1) * BK;
            uint32_t sa = sbase + G2_OFF_A + s * STA + so;
            uint32_t sb = sbase + G2_OFF_B + s * STB + so;
            cpa16(sa, ag0 + kt);
            cpa16(sa + RS64, ag1 + kt);
            cpa16(sb, bg + kt);
        }
        cpa_commit();

        int st = it & (NSTAGE - 1);
        uint32_t abase = sbase + G2_OFF_A + st * STA + a_lo;
        uint32_t bbase = sbase + G2_OFF_B + st * STB + b_lo;
#pragma unroll
        for (int kk = 0; kk < BK; kk += 16) {
            uint32_t a[2][4];
#pragma unroll
            for (int mt = 0; mt < 2; mt++)
                ldsm4(a[mt], abase + mt * 16 * 80 + kk * 2);
            uint32_t bf[2][4];
#pragma unroll
            for (int p = 0; p < 2; p++)
                ldsm4(bf[p], bbase + p * 16 * 80 + kk * 2);
#pragma unroll
            for (int p = 0; p < 2; p++)
#pragma unroll
                for (int mt = 0; mt < 2; mt++) {
                    mma_f16(acc[mt][2*p],   a[mt], &bf[p][0]);
                    mma_f16(acc[mt][2*p+1], a[mt], &bf[p][2]);
                }
        }
    }

    // epilogue: plain stores of unweighted partials
#pragma unroll
    for (int mt = 0; mt < 2; mt++) {
        int m_lo = wm + mt * 16 + fr;
        int m_hi = m_lo + 8;
#pragma unroll
        for (int nt = 0; nt < 4; nt++) {
            int col = nb + wn + nt * 8 + fc * 2;
            if (m_lo < mcnt) {
                float2 v = make_float2(acc[mt][nt][0], acc[mt][nt][1]);
                *(float2*)&g_part[(size_t)(row0 + m_lo) * HDIM + col] = v;
            }
            if (m_hi < mcnt) {
                float2 v = make_float2(acc[mt][nt][2], acc[mt][nt][3]);
                *(float2*)&g_part[(size_t)(row0 + m_hi) * HDIM + col] = v;
            }
        }
    }
}

// ---------------- launch ----------------
extern "C" void kernel_launch(void* const* d_in, const int* in_sizes, int n_in,
                              void* d_out, int out_size) {
    const float* X  = (const float*)d_in[0];  // [T,H]
    const float* RL = (const float*)d_in[1];  // [T,E]
    const float* W1 = (const float*)d_in[2];  // [E,I,H]
    const float* W3 = (const float*)d_in[3];  // [E,I,H]
    const float* W2 = (const float*)d_in[4];  // [E,H,I]
    float* out = (float*)d_out;               // [T,H]

    cudaFuncSetAttribute(k_gemm1, cudaFuncAttributeMaxDynamicSharedMemorySize, G1_SMEM);
    cudaFuncSetAttribute(k_gemm2, cudaFuncAttributeMaxDynamicSharedMemorySize, G2_SMEM);

    k_cvt_all<<<2048, 256>>>(X, W1, W3, W2);         // 1
    k_router<<<NTOK / 256, 256>>>(RL);               // 2
    k_prep_scatter<<<1, 256>>>();                    // 3

    dim3 g1(IDIM / BN, MAX_TILES);                   // 4: 44 x 136  <- ncu capture slot
    k_gemm1<<<g1, 256, G1_SMEM>>>();

    dim3 g2(HDIM / BN, MAX_TILES);                   // 5: 16 x 136
    k_gemm2<<<g2, 256, G2_SMEM>>>();

    k_gather<<<2048, 256>>>(out);                    // 6
}